// round 5
// baseline (speedup 1.0000x reference)
#include <cuda_runtime.h>

// ReduceBoundingBoxes: decode + threshold + stable sort + greedy NMS.
// 3-launch pipeline:
//   KA1 (chip-wide): decode + compact valid entries + zero output
//   KA2 (chip-wide): stable rank -> sorted boxes/scores
//   KD  (1 block)  : on-the-fly survivor-sparse chunked NMS + scatter
//
// No precomputed suppression matrix: per 64-chunk, warps ballot the intra-
// chunk IoU sub-matrix, a single lane resolves greedy deps via ffs over the
// *kept* bits only, and all 1024 threads apply the (few) survivors to future
// boxes by direct IoU. Work scales with survivors, not with M.

#define NCELL   9216
#define PDIM    96
#define WIDTHF  3072.0f
#define HEIGHTF 2304.0f
#define XPSF    32.0f    // multiplies ROW index (P dim)
#define YPSF    24.0f    // multiplies COL index (Q dim)
#define MAXNW   144      // ceil(9216/64)

// -------- global scratch (static device memory) ----------------------------
__device__ int    g_cnt;
__device__ float  g_cscore[NCELL];
__device__ float4 g_cbox[NCELL];
__device__ int    g_corig[NCELL];
__device__ float  g_sscore[NCELL];
__device__ float4 g_sbox[NCELL];

// ---------------------------------------------------------------------------
// KA1: chip-wide decode + compaction + zero output. One thread per cell.
// g_cnt is zero on entry: statically initialized for launch 1, reset by KD
// at the end of every replay.
// ---------------------------------------------------------------------------
__global__ void ka1_decode(const float* __restrict__ x, float* __restrict__ out)
{
    int c = blockIdx.x * blockDim.x + threadIdx.x;   // 0..9215

    // zero output: 46080 floats = 11520 float4 over 9216 threads
    for (int i = c; i < (NCELL * 5) / 4; i += NCELL)
        ((float4*)out)[i] = make_float4(0.f, 0.f, 0.f, 0.f);

    float s = x[c];
    if (s > 0.9f) {
        int   p  = c / PDIM;
        int   q  = c - p * PDIM;
        float ii = (float)p * XPSF;
        float jj = (float)q * YPSF;
        float v1 = x[1 * NCELL + c];
        float v2 = x[2 * NCELL + c];
        float v3 = x[3 * NCELL + c];
        float v4 = x[4 * NCELL + c];
        float bx1 = v1 * WIDTHF  + ii;
        float by1 = v2 * HEIGHTF + jj;
        float bx2 = (v3 - v1) * WIDTHF  + ii;
        float by2 = (v4 - v2) * HEIGHTF + jj;
        int k = atomicAdd(&g_cnt, 1);
        g_cscore[k] = s;
        g_cbox[k]   = make_float4(bx1, by1, bx2, by2);
        g_corig[k]  = c;
    }
}

// ---------------------------------------------------------------------------
// KA2: chip-wide stable rank (score desc, orig asc). Block b owns k in
// [b*256, b*256+256); blocks beyond M exit. Active blocks stage all M
// (score, orig) pairs in SMEM.
// ---------------------------------------------------------------------------
extern __shared__ unsigned char ka2_smem[];

__global__ void ka2_rank()
{
    const int M = g_cnt;
    const int kbase = blockIdx.x * blockDim.x;
    if (kbase >= M) return;

    float* sc = (float*)ka2_smem;              // [M]
    int*   so = (int*)(ka2_smem + NCELL * 4);  // [M]

    for (int i = threadIdx.x; i < M; i += blockDim.x) {
        sc[i] = g_cscore[i];
        so[i] = g_corig[i];
    }
    __syncthreads();

    const int k = kbase + threadIdx.x;
    if (k < M) {
        float sk = sc[k];
        int   ok = so[k];
        int   r  = 0;
        for (int j = 0; j < M; j++) {
            float sj = sc[j];
            r += (sj > sk) || (sj == sk && so[j] < ok);
        }
        g_sbox[r]   = g_cbox[k];
        g_sscore[r] = sk;
    }
}

// ---------------------------------------------------------------------------
// KD: single block, survivor-sparse greedy NMS + scatter.
// Dynamic SMEM: boxes float4[NCELL] (worst case 144 KB).
// ---------------------------------------------------------------------------
extern __shared__ float4 kd_sbox[];

__device__ __forceinline__ bool iou_gt(float4 a, float4 b)
{
    float aa = (a.z - a.x) * (a.w - a.y);
    float ab = (b.z - b.x) * (b.w - b.y);
    float iw = fmaxf(fminf(a.z, b.z) - fmaxf(a.x, b.x), 0.0f);
    float ih = fmaxf(fminf(a.w, b.w) - fmaxf(a.y, b.y), 0.0f);
    float inter = iw * ih;
    return inter / (aa + ab - inter + 1e-9f) > 0.5f;
}

__global__ __launch_bounds__(1024, 1) void kd_nms(float* __restrict__ out)
{
    __shared__ unsigned long long skeep[MAXNW];
    __shared__ unsigned long long sup_local[64];

    const int M = g_cnt;
    const int tid  = threadIdx.x;
    const int wid  = tid >> 5;
    const int lane = tid & 31;

    if (M == 0) { if (tid == 0) g_cnt = 0; return; }
    const int nw = (M + 63) >> 6;

    // stage sorted boxes into SMEM
    for (int i = tid; i < M; i += 1024)
        kd_sbox[i] = g_sbox[i];
    if (tid < nw) {
        int nb = M - (tid << 6);
        skeep[tid] = (nb >= 64) ? ~0ull : ((1ull << nb) - 1ull);
    }
    __syncthreads();

    for (int c = 0; c < nw; c++) {
        const int base = c << 6;
        const int nb   = min(64, M - base);

        // --- ballot phase: intra-chunk IoU sub-matrix (64x64 bits) ---
        // warp w owns rows 2w and 2w+1; lane l tests columns l and l+32.
        #pragma unroll
        for (int rr = 0; rr < 2; rr++) {
            int b = (wid << 1) | rr;
            if (b < nb) {
                float4 bi = kd_sbox[base + b];         // broadcast read
                int j1 = base + lane;
                int j2 = base + lane + 32;
                bool p1 = (lane > b)        && (lane      < nb) && iou_gt(bi, kd_sbox[j1]);
                bool p2 = (lane + 32 > b)   && (lane + 32 < nb) && iou_gt(bi, kd_sbox[j2]);
                unsigned lo = __ballot_sync(0xFFFFFFFFu, p1);
                unsigned hi = __ballot_sync(0xFFFFFFFFu, p2);
                if (lane == 0)
                    sup_local[b] = (unsigned long long)lo |
                                   ((unsigned long long)hi << 32);
            }
        }
        __syncthreads();

        // --- resolve: greedy over kept bits only (ffs walk) ---
        if (tid == 0) {
            unsigned long long kw  = skeep[c];
            unsigned long long rem = kw;
            while (rem) {
                int b = __ffsll((long long)rem) - 1;
                unsigned long long s = sup_local[b];   // bits strictly > b
                kw  &= ~s;
                rem &= ~s;
                rem &= rem - 1;                        // clear bit b (processed)
            }
            skeep[c] = kw;
        }
        __syncthreads();

        // --- apply: survivors suppress future boxes by direct IoU ---
        const unsigned long long kw = skeep[c];
        if (kw) {
            for (int j = base + 64 + tid; j < M; j += 1024) {
                float4 bj = kd_sbox[j];
                bool supp = false;
                unsigned long long t = kw;
                while (t) {
                    int b = __ffsll((long long)t) - 1;
                    t &= t - 1;
                    if (iou_gt(kd_sbox[base + b], bj)) { supp = true; break; }
                }
                if (supp)
                    atomicAnd(&skeep[j >> 6], ~(1ull << (j & 63)));
            }
        }
        __syncthreads();
    }

    // --- scatter kept rows (output zeroed by KA1) ---
    for (int r = tid; r < M; r += 1024) {
        if ((skeep[r >> 6] >> (r & 63)) & 1ull) {
            float4 b = kd_sbox[r];
            out[r * 5 + 0] = g_sscore[r];
            out[r * 5 + 1] = b.x;
            out[r * 5 + 2] = b.y;
            out[r * 5 + 3] = b.z - b.x;
            out[r * 5 + 4] = b.w - b.y;
        }
    }

    // reset compaction counter for the next replay
    __syncthreads();
    if (tid == 0) g_cnt = 0;
}

// ---------------------------------------------------------------------------
extern "C" void kernel_launch(void* const* d_in, const int* in_sizes, int n_in,
                              void* d_out, int out_size)
{
    (void)in_sizes; (void)n_in; (void)out_size;
    const float* x   = (const float*)d_in[0];
    float*       out = (float*)d_out;

    cudaFuncSetAttribute(ka2_rank,
                         cudaFuncAttributeMaxDynamicSharedMemorySize,
                         NCELL * 8);
    cudaFuncSetAttribute(kd_nms,
                         cudaFuncAttributeMaxDynamicSharedMemorySize,
                         NCELL * 16);

    ka1_decode<<<NCELL / 256, 256>>>(x, out);
    ka2_rank<<<NCELL / 256, 256, NCELL * 8>>>();
    kd_nms<<<1, 1024, NCELL * 16>>>(out);
}

// round 6
// speedup vs baseline: 2.4127x; 2.4127x over previous
#include <cuda_runtime.h>

// ReduceBoundingBoxes: decode + threshold + stable sort + greedy NMS.
// SINGLE persistent kernel, 36 blocks x 1024 threads (all co-resident),
// software grid barriers between phases:
//   P0: zero output + decode + compact (global atomic)
//   P1: stable rank -> sorted boxes/scores
//   P2: suppression bit-matrix (chip-wide-ish: 36864 threads)
//   P3: block 0 only: chunked greedy scan (pipelined, zero-skip) + scatter
//   end: block 0 resets barrier + counter for the next graph replay.

#define NCELL   9216
#define PDIM    96
#define WIDTHF  3072.0f
#define HEIGHTF 2304.0f
#define XPSF    32.0f    // multiplies ROW index (P dim)
#define YPSF    24.0f    // multiplies COL index (Q dim)
#define MAXNW   144      // ceil(9216/64)
#define SUP_SMEM_WORDS 22528   // 180224 B dynamic SMEM (scan fast path)
#define NBLK    36
#define NTHR    1024

// -------- global scratch (static device memory) ----------------------------
__device__ int    g_cnt;    // zero-init; reset at end of every run
__device__ int    g_bar;    // grid-barrier arrivals; reset at end of every run
__device__ float  g_cscore[NCELL];
__device__ float4 g_cbox[NCELL];
__device__ int    g_corig[NCELL];
__device__ float  g_sscore[NCELL];
__device__ float4 g_sbox[NCELL];
__device__ unsigned long long g_sup[(size_t)NCELL * MAXNW];

extern __shared__ unsigned char dyn_smem[];

__device__ __forceinline__ void grid_barrier(int target)
{
    __syncthreads();
    if (threadIdx.x == 0) {
        __threadfence();
        atomicAdd(&g_bar, 1);
        while (*(volatile int*)&g_bar < target) { }
    }
    __syncthreads();
    __threadfence();
}

__global__ __launch_bounds__(NTHR, 1)
void rbb_fused(const float* __restrict__ x, float* __restrict__ out)
{
    const int tid  = threadIdx.x;
    const int bid  = blockIdx.x;
    const int gtid = bid * NTHR + tid;
    const int GT   = NBLK * NTHR;          // 36864

    // ---------------- P0: zero output + decode + compact -------------------
    for (int i = gtid; i < (NCELL * 5) / 4; i += GT)
        ((float4*)out)[i] = make_float4(0.f, 0.f, 0.f, 0.f);

    if (gtid < NCELL) {
        int   c = gtid;
        float s = x[c];
        if (s > 0.9f) {
            int   p  = c / PDIM;
            int   q  = c - p * PDIM;
            float ii = (float)p * XPSF;
            float jj = (float)q * YPSF;
            float v1 = x[1 * NCELL + c];
            float v2 = x[2 * NCELL + c];
            float v3 = x[3 * NCELL + c];
            float v4 = x[4 * NCELL + c];
            float bx1 = v1 * WIDTHF  + ii;
            float by1 = v2 * HEIGHTF + jj;
            float bx2 = (v3 - v1) * WIDTHF  + ii;
            float by2 = (v4 - v2) * HEIGHTF + jj;
            int k = atomicAdd(&g_cnt, 1);
            g_cscore[k] = s;
            g_cbox[k]   = make_float4(bx1, by1, bx2, by2);
            g_corig[k]  = c;
        }
    }
    grid_barrier(1 * NBLK);

    const int M  = *(volatile int*)&g_cnt;
    const int nw = (M + 63) >> 6;

    // ---------------- P1: stable rank (score desc, orig asc) ---------------
    {
        const int kbase = bid * NTHR;
        if (kbase < M) {
            float* sc = (float*)dyn_smem;               // [M]
            int*   so = (int*)(dyn_smem + NCELL * 4);   // [M]
            for (int i = tid; i < M; i += NTHR) {
                sc[i] = g_cscore[i];
                so[i] = g_corig[i];
            }
            __syncthreads();
            const int k = kbase + tid;
            if (k < M) {
                float sk = sc[k];
                int   ok = so[k];
                int   r  = 0;
                for (int j = 0; j < M; j++) {
                    float sj = sc[j];
                    r += (sj > sk) || (sj == sk && so[j] < ok);
                }
                g_sbox[r]   = g_cbox[k];
                g_sscore[r] = sk;
            }
        }
    }
    grid_barrier(2 * NBLK);

    // ---------------- P2: suppression bit-matrix ----------------------------
    {
        const int total = M * nw;
        for (int it = gtid; it < total; it += GT) {
            int i = it / nw;
            int w = it - i * nw;
            if (w < (i >> 6)) continue;            // never read by the scan

            float4 bi = g_sbox[i];
            float  ai = (bi.z - bi.x) * (bi.w - bi.y);

            int base = w << 6;
            int nb   = min(64, M - base);
            unsigned long long bits = 0;
            for (int b = 0; b < nb; b++) {
                int j = base + b;
                if (j > i) {
                    float4 bj = g_sbox[j];
                    float  aj = (bj.z - bj.x) * (bj.w - bj.y);
                    float iw = fmaxf(fminf(bi.z, bj.z) - fmaxf(bi.x, bj.x), 0.0f);
                    float ih = fmaxf(fminf(bi.w, bj.w) - fmaxf(bi.y, bj.y), 0.0f);
                    float inter = iw * ih;
                    float iou = inter / (ai + aj - inter + 1e-9f);
                    if (iou > 0.5f) bits |= (1ull << b);
                }
            }
            g_sup[it] = bits;
        }
    }
    grid_barrier(3 * NBLK);

    // ---------------- P3: block 0 scan + scatter ----------------------------
    if (bid == 0 && M > 0) {
        __shared__ unsigned long long skeep[MAXNW];
        unsigned long long* ssup = (unsigned long long*)dyn_smem;

        const int Mr   = nw << 6;
        const bool fast = ((size_t)Mr * nw) <= SUP_SMEM_WORDS;

        if (fast) {
            const int used = M * nw;
            for (int i = tid; i < used; i += NTHR)
                ssup[i] = g_sup[i];
            for (int i = used + tid; i < Mr * nw; i += NTHR)
                ssup[i] = 0ull;
        }
        if (tid < nw) {
            int nb = M - (tid << 6);
            skeep[tid] = (nb >= 64) ? ~0ull : ((1ull << nb) - 1ull);
        }
        __syncthreads();

        if (tid < 32) {
            const int lane = tid;
            for (int c = 0; c < nw; c++) {
                const int base = c << 6;

                if (lane == 0) {
                    unsigned long long kw = skeep[c];
                    #pragma unroll 1
                    for (int b0 = 0; b0 < 64; b0 += 8) {
                        unsigned long long s0, s1, s2, s3, s4, s5, s6, s7;
                        if (fast) {
                            const unsigned long long* p = &ssup[(size_t)(base + b0) * nw + c];
                            s0 = p[0*nw]; s1 = p[1*nw]; s2 = p[2*nw]; s3 = p[3*nw];
                            s4 = p[4*nw]; s5 = p[5*nw]; s6 = p[6*nw]; s7 = p[7*nw];
                        } else {
                            const unsigned long long* p = &g_sup[(size_t)(base + b0) * nw + c];
                            s0 = p[0*nw]; s1 = p[1*nw]; s2 = p[2*nw]; s3 = p[3*nw];
                            s4 = p[4*nw]; s5 = p[5*nw]; s6 = p[6*nw]; s7 = p[7*nw];
                        }
                        // zero-skip: if no row in this batch suppresses anyone,
                        // the whole dependent gating chain is a no-op.
                        if ((s0 | s1 | s2 | s3 | s4 | s5 | s6 | s7) != 0ull) {
                            kw &= ~(((kw >> (b0+0)) & 1ull) ? s0 : 0ull);
                            kw &= ~(((kw >> (b0+1)) & 1ull) ? s1 : 0ull);
                            kw &= ~(((kw >> (b0+2)) & 1ull) ? s2 : 0ull);
                            kw &= ~(((kw >> (b0+3)) & 1ull) ? s3 : 0ull);
                            kw &= ~(((kw >> (b0+4)) & 1ull) ? s4 : 0ull);
                            kw &= ~(((kw >> (b0+5)) & 1ull) ? s5 : 0ull);
                            kw &= ~(((kw >> (b0+6)) & 1ull) ? s6 : 0ull);
                            kw &= ~(((kw >> (b0+7)) & 1ull) ? s7 : 0ull);
                        }
                    }
                    skeep[c] = kw;
                }
                __syncwarp();

                const unsigned long long kw = skeep[c];
                if (kw) {
                    for (int w = c + 1 + lane; w < nw; w += 32) {
                        unsigned long long acc = 0;
                        if (fast) {
                            const unsigned long long* p = &ssup[(size_t)base * nw + w];
                            #pragma unroll
                            for (int b = 0; b < 64; b++)
                                acc |= ((kw >> b) & 1ull) ? p[(size_t)b * nw] : 0ull;
                        } else {
                            const unsigned long long* p = &g_sup[(size_t)base * nw + w];
                            #pragma unroll 8
                            for (int b = 0; b < 64; b++)
                                acc |= ((kw >> b) & 1ull) ? p[(size_t)b * nw] : 0ull;
                        }
                        skeep[w] &= ~acc;
                    }
                }
                __syncwarp();
            }
        }
        __syncthreads();

        // scatter kept rows (output zeroed in P0)
        for (int r = tid; r < M; r += NTHR) {
            if ((skeep[r >> 6] >> (r & 63)) & 1ull) {
                float4 b = g_sbox[r];
                out[r * 5 + 0] = g_sscore[r];
                out[r * 5 + 1] = b.x;
                out[r * 5 + 2] = b.y;
                out[r * 5 + 3] = b.z - b.x;
                out[r * 5 + 4] = b.w - b.y;
            }
        }
    }

    // ---------------- final: reset counters for next replay -----------------
    // Everyone arrives; only block 0 waits for all arrivals, then resets.
    __syncthreads();
    if (tid == 0) {
        __threadfence();
        atomicAdd(&g_bar, 1);
        if (bid == 0) {
            while (*(volatile int*)&g_bar < 4 * NBLK) { }
            g_cnt = 0;
            g_bar = 0;
            __threadfence();
        }
    }
}

// ---------------------------------------------------------------------------
extern "C" void kernel_launch(void* const* d_in, const int* in_sizes, int n_in,
                              void* d_out, int out_size)
{
    (void)in_sizes; (void)n_in; (void)out_size;
    const float* x   = (const float*)d_in[0];
    float*       out = (float*)d_out;

    cudaFuncSetAttribute(rbb_fused,
                         cudaFuncAttributeMaxDynamicSharedMemorySize,
                         SUP_SMEM_WORDS * 8);

    rbb_fused<<<NBLK, NTHR, SUP_SMEM_WORDS * 8>>>(x, out);
}

// round 7
// speedup vs baseline: 3.9814x; 1.6502x over previous
#include <cuda_runtime.h>

// ReduceBoundingBoxes: decode + threshold + stable sort + greedy NMS.
// SINGLE persistent kernel, 36 blocks x 1024 threads, software grid barriers:
//   P0: zero output + zero nz bitmap + decode + compact
//   P1: stable rank (k strided across blocks: 1 warp/SM of real work)
//   P2: suppression bit-matrix + nonzero-row bitmap g_nz
//   P3: block 0: sparse chunked greedy scan (ffs over kept&nz rows) + scatter
//   end: block 0 resets barrier + counter for next graph replay.

#define NCELL   9216
#define PDIM    96
#define WIDTHF  3072.0f
#define HEIGHTF 2304.0f
#define XPSF    32.0f    // multiplies ROW index (P dim)
#define YPSF    24.0f    // multiplies COL index (Q dim)
#define MAXNW   144      // ceil(9216/64)
#define SUP_SMEM_WORDS 22528   // 180224 B dynamic SMEM (scan fast path)
#define NBLK    36
#define NTHR    1024

// -------- global scratch (static device memory) ----------------------------
__device__ int    g_cnt;    // zero-init; reset at end of every run
__device__ int    g_bar;    // grid-barrier arrivals; reset at end of every run
__device__ float  g_cscore[NCELL];
__device__ float4 g_cbox[NCELL];
__device__ int    g_corig[NCELL];
__device__ float  g_sscore[NCELL];
__device__ float4 g_sbox[NCELL];
__device__ unsigned long long g_nz[MAXNW];            // nonzero-row bitmap
__device__ unsigned long long g_sup[(size_t)NCELL * MAXNW];

extern __shared__ unsigned char dyn_smem[];

__device__ __forceinline__ void grid_barrier(int target)
{
    __syncthreads();
    if (threadIdx.x == 0) {
        __threadfence();
        atomicAdd(&g_bar, 1);
        while (*(volatile int*)&g_bar < target) { }
    }
    __syncthreads();
    __threadfence();
}

__global__ __launch_bounds__(NTHR, 1)
void rbb_fused(const float* __restrict__ x, float* __restrict__ out)
{
    const int tid  = threadIdx.x;
    const int bid  = blockIdx.x;
    const int gtid = bid * NTHR + tid;
    const int GT   = NBLK * NTHR;          // 36864

    // ---------------- P0: zero output + nz bitmap, decode + compact ---------
    for (int i = gtid; i < (NCELL * 5) / 4; i += GT)
        ((float4*)out)[i] = make_float4(0.f, 0.f, 0.f, 0.f);
    if (gtid < MAXNW) g_nz[gtid] = 0ull;

    if (gtid < NCELL) {
        int   c = gtid;
        float s = x[c];
        if (s > 0.9f) {
            int   p  = c / PDIM;
            int   q  = c - p * PDIM;
            float ii = (float)p * XPSF;
            float jj = (float)q * YPSF;
            float v1 = x[1 * NCELL + c];
            float v2 = x[2 * NCELL + c];
            float v3 = x[3 * NCELL + c];
            float v4 = x[4 * NCELL + c];
            float bx1 = v1 * WIDTHF  + ii;
            float by1 = v2 * HEIGHTF + jj;
            float bx2 = (v3 - v1) * WIDTHF  + ii;
            float by2 = (v4 - v2) * HEIGHTF + jj;
            int k = atomicAdd(&g_cnt, 1);
            g_cscore[k] = s;
            g_cbox[k]   = make_float4(bx1, by1, bx2, by2);
            g_corig[k]  = c;
        }
    }
    grid_barrier(1 * NBLK);

    const int M  = *(volatile int*)&g_cnt;
    const int nw = (M + 63) >> 6;

    // ---------------- P1: stable rank (score desc, orig asc) ----------------
    // k = tid*NBLK + bid: every block gets ~M/NBLK ranks (~1 warp of work).
    {
        float* sc = (float*)dyn_smem;               // [M]
        int*   so = (int*)(dyn_smem + NCELL * 4);   // [M]
        for (int i = tid; i < M; i += NTHR) {
            sc[i] = g_cscore[i];
            so[i] = g_corig[i];
        }
        __syncthreads();
        const int k = tid * NBLK + bid;
        if (k < M) {
            float sk = sc[k];
            int   ok = so[k];
            int   r  = 0;
            for (int j = 0; j < M; j++) {
                float sj = sc[j];
                r += (sj > sk) || (sj == sk && so[j] < ok);
            }
            g_sbox[r]   = g_cbox[k];
            g_sscore[r] = sk;
        }
    }
    grid_barrier(2 * NBLK);

    // ---------------- P2: suppression bit-matrix + nonzero-row bitmap -------
    {
        const int total = M * nw;
        for (int it = gtid; it < total; it += GT) {
            int i = it / nw;
            int w = it - i * nw;
            if (w < (i >> 6)) continue;            // never read by the scan

            float4 bi = g_sbox[i];
            float  ai = (bi.z - bi.x) * (bi.w - bi.y);

            int base = w << 6;
            int nb   = min(64, M - base);
            unsigned long long bits = 0;
            for (int b = 0; b < nb; b++) {
                int j = base + b;
                if (j > i) {
                    float4 bj = g_sbox[j];
                    float  aj = (bj.z - bj.x) * (bj.w - bj.y);
                    float iw = fmaxf(fminf(bi.z, bj.z) - fmaxf(bi.x, bj.x), 0.0f);
                    float ih = fmaxf(fminf(bi.w, bj.w) - fmaxf(bi.y, bj.y), 0.0f);
                    float inter = iw * ih;
                    float iou = inter / (ai + aj - inter + 1e-9f);
                    if (iou > 0.5f) bits |= (1ull << b);
                }
            }
            g_sup[it] = bits;
            if (bits)
                atomicOr(&g_nz[i >> 6], 1ull << (i & 63));
        }
    }
    grid_barrier(3 * NBLK);

    // ---------------- P3: block 0 sparse scan + scatter ----------------------
    if (bid == 0 && M > 0) {
        __shared__ unsigned long long skeep[MAXNW];
        __shared__ unsigned long long snz[MAXNW];
        unsigned long long* ssup = (unsigned long long*)dyn_smem;

        const bool fast = (M * nw) <= SUP_SMEM_WORDS;

        if (fast) {
            for (int i = tid; i < M * nw; i += NTHR)
                ssup[i] = g_sup[i];
        }
        if (tid < nw) {
            int nb = M - (tid << 6);
            skeep[tid] = (nb >= 64) ? ~0ull : ((1ull << nb) - 1ull);
            snz[tid]   = g_nz[tid];
        }
        __syncthreads();

        if (tid < 32) {
            const int lane = tid;
            for (int c = 0; c < nw; c++) {
                const int base = c << 6;

                // --- resolve: walk only kept rows that suppress somebody ---
                if (lane == 0) {
                    unsigned long long kw  = skeep[c];
                    unsigned long long rem = kw & snz[c];
                    while (rem) {
                        int b = __ffsll((long long)rem) - 1;
                        unsigned long long s = fast
                            ? ssup[(size_t)(base + b) * nw + c]
                            : g_sup[(size_t)(base + b) * nw + c];
                        kw  &= ~s;          // bits in s are strictly > b
                        rem &= ~s;
                        rem &= rem - 1;     // clear bit b (b is lowest)
                    }
                    skeep[c] = kw;
                }
                __syncwarp();

                // --- apply: only suppressing survivors hit future words ---
                const unsigned long long kwnz = skeep[c] & snz[c];
                if (kwnz) {
                    for (int w = c + 1 + lane; w < nw; w += 32) {
                        unsigned long long acc = 0, t = kwnz;
                        while (t) {
                            int b = __ffsll((long long)t) - 1;
                            t &= t - 1;
                            acc |= fast ? ssup[(size_t)(base + b) * nw + w]
                                        : g_sup[(size_t)(base + b) * nw + w];
                        }
                        skeep[w] &= ~acc;
                    }
                }
                __syncwarp();
            }
        }
        __syncthreads();

        // scatter kept rows (output zeroed in P0)
        for (int r = tid; r < M; r += NTHR) {
            if ((skeep[r >> 6] >> (r & 63)) & 1ull) {
                float4 b = g_sbox[r];
                out[r * 5 + 0] = g_sscore[r];
                out[r * 5 + 1] = b.x;
                out[r * 5 + 2] = b.y;
                out[r * 5 + 3] = b.z - b.x;
                out[r * 5 + 4] = b.w - b.y;
            }
        }
    }

    // ---------------- final: reset counters for next replay ------------------
    __syncthreads();
    if (tid == 0) {
        __threadfence();
        atomicAdd(&g_bar, 1);
        if (bid == 0) {
            while (*(volatile int*)&g_bar < 4 * NBLK) { }
            g_cnt = 0;
            g_bar = 0;
            __threadfence();
        }
    }
}

// ---------------------------------------------------------------------------
extern "C" void kernel_launch(void* const* d_in, const int* in_sizes, int n_in,
                              void* d_out, int out_size)
{
    (void)in_sizes; (void)n_in; (void)out_size;
    const float* x   = (const float*)d_in[0];
    float*       out = (float*)d_out;

    cudaFuncSetAttribute(rbb_fused,
                         cudaFuncAttributeMaxDynamicSharedMemorySize,
                         SUP_SMEM_WORDS * 8);

    rbb_fused<<<NBLK, NTHR, SUP_SMEM_WORDS * 8>>>(x, out);
}

// round 8
// speedup vs baseline: 4.9438x; 1.2417x over previous
#include <cuda_runtime.h>

// ReduceBoundingBoxes: decode + threshold + stable sort + greedy NMS.
// SINGLE persistent kernel, 36 blocks x 1024 threads, software grid barriers.
// Key insight: a pair can suppress only if BOTH boxes have positive width and
// height (else inter==0 -> iou<=0). ~75% of boxes are degenerate -> restrict
// the O(A^2) IoU work and the greedy scan to the ~25% "active" subsequence.
//   P0: zero output + decode + compact (global atomic)
//   P1: stable rank -> sorted boxes/scores (k strided across blocks)
//   P2: block 0: compact active boxes in rank order (atomic + rank-count)
//   P3: all blocks: suppression bit-matrix over ACTIVES + nz bitmap
//   P4: block 0: sparse chunked greedy scan over actives + scatter
//   end: block 0 resets barrier + counter for next graph replay.

#define NCELL   9216
#define PDIM    96
#define WIDTHF  3072.0f
#define HEIGHTF 2304.0f
#define XPSF    32.0f    // multiplies ROW index (P dim)
#define YPSF    24.0f    // multiplies COL index (Q dim)
#define MAXNW   144      // ceil(9216/64)
#define SUP_SMEM_WORDS 22528   // 180224 B dynamic SMEM (scan fast path)
#define NBLK    36
#define NTHR    1024

// -------- global scratch (static device memory) ----------------------------
__device__ int    g_cnt;    // valid-box count; reset at end of every run
__device__ int    g_acnt;   // active-box count; written each run in P2
__device__ int    g_bar;    // grid-barrier arrivals; reset at end of every run
__device__ float  g_cscore[NCELL];
__device__ float4 g_cbox[NCELL];     // P0: decoded boxes; P2+: reused as abox
__device__ int    g_corig[NCELL];    // P0: orig cell;     P2: unordered ranks
__device__ int    g_arank[NCELL];    // rank (sorted idx) of active a
__device__ float  g_sscore[NCELL];
__device__ float4 g_sbox[NCELL];
__device__ unsigned long long g_nz[MAXNW];            // nonzero-row bitmap (actives)
__device__ unsigned long long g_sup[(size_t)NCELL * MAXNW];

extern __shared__ unsigned char dyn_smem[];

__device__ __forceinline__ void grid_barrier(int target)
{
    __syncthreads();
    if (threadIdx.x == 0) {
        __threadfence();
        atomicAdd(&g_bar, 1);
        while (*(volatile int*)&g_bar < target) { }
    }
    __syncthreads();
    __threadfence();
}

__global__ __launch_bounds__(NTHR, 1)
void rbb_fused(const float* __restrict__ x, float* __restrict__ out)
{
    const int tid  = threadIdx.x;
    const int bid  = blockIdx.x;
    const int gtid = bid * NTHR + tid;
    const int GT   = NBLK * NTHR;          // 36864

    // ---------------- P0: zero output + nz, decode + compact -----------------
    for (int i = gtid; i < (NCELL * 5) / 4; i += GT)
        ((float4*)out)[i] = make_float4(0.f, 0.f, 0.f, 0.f);
    if (gtid < MAXNW) g_nz[gtid] = 0ull;

    if (gtid < NCELL) {
        int   c = gtid;
        float s = x[c];
        if (s > 0.9f) {
            int   p  = c / PDIM;
            int   q  = c - p * PDIM;
            float ii = (float)p * XPSF;
            float jj = (float)q * YPSF;
            float v1 = x[1 * NCELL + c];
            float v2 = x[2 * NCELL + c];
            float v3 = x[3 * NCELL + c];
            float v4 = x[4 * NCELL + c];
            float bx1 = v1 * WIDTHF  + ii;
            float by1 = v2 * HEIGHTF + jj;
            float bx2 = (v3 - v1) * WIDTHF  + ii;
            float by2 = (v4 - v2) * HEIGHTF + jj;
            int k = atomicAdd(&g_cnt, 1);
            g_cscore[k] = s;
            g_cbox[k]   = make_float4(bx1, by1, bx2, by2);
            g_corig[k]  = c;
        }
    }
    grid_barrier(1 * NBLK);

    const int M = *(volatile int*)&g_cnt;

    // ---------------- P1: stable rank (score desc, orig asc) ----------------
    {
        float* sc = (float*)dyn_smem;               // [M]
        int*   so = (int*)(dyn_smem + NCELL * 4);   // [M]
        for (int i = tid; i < M; i += NTHR) {
            sc[i] = g_cscore[i];
            so[i] = g_corig[i];
        }
        __syncthreads();
        const int k = tid * NBLK + bid;
        if (k < M) {
            float sk = sc[k];
            int   ok = so[k];
            int   r  = 0;
            for (int j = 0; j < M; j++) {
                float sj = sc[j];
                r += (sj > sk) || (sj == sk && so[j] < ok);
            }
            g_sbox[r]   = g_cbox[k];
            g_sscore[r] = sk;
        }
    }
    grid_barrier(2 * NBLK);

    // ---------------- P2: block 0: compact actives in rank order -------------
    // active := strictly positive width AND height; only such boxes can
    // suppress or be suppressed (inter>0 needs both boxes positive).
    if (bid == 0) {
        __shared__ int s_acnt;
        int* stmp = (int*)dyn_smem;                 // unordered active ranks
        if (tid == 0) s_acnt = 0;
        __syncthreads();
        for (int r = tid; r < M; r += NTHR) {
            float4 b = g_sbox[r];
            if (b.z > b.x && b.w > b.y) {
                int a = atomicAdd(&s_acnt, 1);
                stmp[a] = r;
            }
        }
        __syncthreads();
        const int A = s_acnt;
        if (tid == 0) g_acnt = A;
        // order actives by rank via counting (ranks are distinct)
        for (int a = tid; a < A; a += NTHR) {
            int ra  = stmp[a];
            int pos = 0;
            for (int b = 0; b < A; b++) pos += stmp[b] < ra;
            g_arank[pos] = ra;
            g_cbox[pos]  = g_sbox[ra];              // g_cbox reused as abox
        }
    }
    grid_barrier(3 * NBLK);

    const int A  = *(volatile int*)&g_acnt;
    const int na = (A + 63) >> 6;

    // ---------------- P3: bit-matrix over actives + nz bitmap ----------------
    {
        const int total = A * na;
        for (int it = gtid; it < total; it += GT) {
            int i = it / na;
            int w = it - i * na;
            if (w < (i >> 6)) continue;            // never read by the scan

            float4 bi = g_cbox[i];
            float  ai = (bi.z - bi.x) * (bi.w - bi.y);

            int base = w << 6;
            int nb   = min(64, A - base);
            unsigned long long bits = 0;
            for (int b = 0; b < nb; b++) {
                int j = base + b;
                if (j > i) {
                    float4 bj = g_cbox[j];
                    float  aj = (bj.z - bj.x) * (bj.w - bj.y);
                    float iw = fmaxf(fminf(bi.z, bj.z) - fmaxf(bi.x, bj.x), 0.0f);
                    float ih = fmaxf(fminf(bi.w, bj.w) - fmaxf(bi.y, bj.y), 0.0f);
                    float inter = iw * ih;
                    float iou = inter / (ai + aj - inter + 1e-9f);
                    if (iou > 0.5f) bits |= (1ull << b);
                }
            }
            g_sup[it] = bits;
            if (bits)
                atomicOr(&g_nz[i >> 6], 1ull << (i & 63));
        }
    }
    grid_barrier(4 * NBLK);

    // ---------------- P4: block 0: sparse scan over actives + scatter --------
    if (bid == 0 && M > 0) {
        __shared__ unsigned long long skeepA[MAXNW];   // keep bits over actives
        __shared__ unsigned long long skeepR[MAXNW];   // keep bits over sorted r
        __shared__ unsigned long long snz[MAXNW];
        unsigned long long* ssup = (unsigned long long*)dyn_smem;

        const bool fast = (A * na) <= SUP_SMEM_WORDS;
        if (fast) {
            for (int i = tid; i < A * na; i += NTHR)
                ssup[i] = g_sup[i];
        }
        const int nwR = (M + 63) >> 6;
        if (tid < MAXNW) {
            if (tid < na) {
                int nb = A - (tid << 6);
                skeepA[tid] = (nb >= 64) ? ~0ull : ((1ull << nb) - 1ull);
                snz[tid]    = g_nz[tid];
            }
            if (tid < nwR) {
                int nb = M - (tid << 6);
                skeepR[tid] = (nb >= 64) ? ~0ull : ((1ull << nb) - 1ull);
            }
        }
        __syncthreads();

        if (tid < 32 && A > 0) {
            const int lane = tid;
            for (int c = 0; c < na; c++) {
                const int base = c << 6;

                // resolve: walk only kept rows that suppress somebody
                if (lane == 0) {
                    unsigned long long kw  = skeepA[c];
                    unsigned long long rem = kw & snz[c];
                    while (rem) {
                        int b = __ffsll((long long)rem) - 1;
                        unsigned long long s = fast
                            ? ssup[(size_t)(base + b) * na + c]
                            : g_sup[(size_t)(base + b) * na + c];
                        kw  &= ~s;          // bits in s are strictly > b
                        rem &= ~s;
                        rem &= rem - 1;     // clear processed (lowest) bit
                    }
                    skeepA[c] = kw;
                }
                __syncwarp();

                // apply: suppressing survivors hit future words
                const unsigned long long kwnz = skeepA[c] & snz[c];
                if (kwnz) {
                    for (int w = c + 1 + lane; w < na; w += 32) {
                        unsigned long long acc = 0, t = kwnz;
                        while (t) {
                            int b = __ffsll((long long)t) - 1;
                            t &= t - 1;
                            acc |= fast ? ssup[(size_t)(base + b) * na + w]
                                        : g_sup[(size_t)(base + b) * na + w];
                        }
                        skeepA[w] &= ~acc;
                    }
                }
                __syncwarp();
            }
        }
        __syncthreads();

        // map suppressed actives back to sorted ranks
        for (int a = tid; a < A; a += NTHR) {
            if (!((skeepA[a >> 6] >> (a & 63)) & 1ull)) {
                int r = g_arank[a];
                atomicAnd(&skeepR[r >> 6], ~(1ull << (r & 63)));
            }
        }
        __syncthreads();

        // scatter kept rows (output zeroed in P0)
        for (int r = tid; r < M; r += NTHR) {
            if ((skeepR[r >> 6] >> (r & 63)) & 1ull) {
                float4 b = g_sbox[r];
                out[r * 5 + 0] = g_sscore[r];
                out[r * 5 + 1] = b.x;
                out[r * 5 + 2] = b.y;
                out[r * 5 + 3] = b.z - b.x;
                out[r * 5 + 4] = b.w - b.y;
            }
        }
    }

    // ---------------- final: reset counters for next replay ------------------
    __syncthreads();
    if (tid == 0) {
        __threadfence();
        atomicAdd(&g_bar, 1);
        if (bid == 0) {
            while (*(volatile int*)&g_bar < 5 * NBLK) { }
            g_cnt = 0;
            g_bar = 0;
            __threadfence();
        }
    }
}

// ---------------------------------------------------------------------------
extern "C" void kernel_launch(void* const* d_in, const int* in_sizes, int n_in,
                              void* d_out, int out_size)
{
    (void)in_sizes; (void)n_in; (void)out_size;
    const float* x   = (const float*)d_in[0];
    float*       out = (float*)d_out;

    cudaFuncSetAttribute(rbb_fused,
                         cudaFuncAttributeMaxDynamicSharedMemorySize,
                         SUP_SMEM_WORDS * 8);

    rbb_fused<<<NBLK, NTHR, SUP_SMEM_WORDS * 8>>>(x, out);
}

// round 9
// speedup vs baseline: 5.0802x; 1.0276x over previous
#include <cuda_runtime.h>

// ReduceBoundingBoxes: decode + threshold + stable sort + greedy NMS.
// SINGLE persistent kernel, 18 blocks x 1024 threads, THREE software grid
// barriers. Only boxes with positive width AND height ("actives") can
// suppress / be suppressed; NMS runs on that subsequence only.
//   P0: zero output + nz bitmap, decode + compact (global atomic)
//   B1
//   P1: stable rank (score desc, orig asc) -> sorted boxes/scores
//   B2
//   P2: per-block (redundant, deterministic): ballot-bitmap compaction of
//       actives into block SMEM; then suppression bit-matrix over actives
//       (items strided across the grid) + nonzero-row bitmap
//   B3
//   P4: block 0: sparse chunked greedy scan + map back + scatter
//   end: non-0 blocks post a final arrive and exit; block 0 waits, resets.

#define NCELL   9216
#define PDIM    96
#define WIDTHF  3072.0f
#define HEIGHTF 2304.0f
#define XPSF    32.0f    // multiplies ROW index (P dim)
#define YPSF    24.0f    // multiplies COL index (Q dim)
#define MAXNW   144      // ceil(9216/64)
#define NBLK    18
#define NTHR    1024
#define GTOT    (NBLK * NTHR)
#define SSUP_WORDS 18432          // 147456 B overlay for scan fast path

// -------- global scratch (static device memory) ----------------------------
__device__ int    g_cnt;    // valid-box count; reset at end of every run
__device__ int    g_bar;    // grid-barrier arrivals; reset at end of every run
__device__ float  g_cscore[NCELL];
__device__ float4 g_cbox[NCELL];
__device__ int    g_corig[NCELL];
__device__ float  g_sscore[NCELL];
__device__ float4 g_sbox[NCELL];
__device__ unsigned long long g_nz[MAXNW];
__device__ unsigned long long g_sup[(size_t)NCELL * MAXNW];

// dynamic SMEM layout (184320 B):
//   [0      , 147456): P1 sc/so | P2 abox[A] float4 | P4 ssup overlay
//   [147456 , 184320): P2/P4 arank[A] int (persists P2 -> P4 in block 0)
extern __shared__ unsigned char dyn_smem[];

__device__ __forceinline__ void grid_barrier(int target)
{
    __syncthreads();
    if (threadIdx.x == 0) {
        __threadfence();
        atomicAdd(&g_bar, 1);
        while (*(volatile int*)&g_bar < target) { }
    }
    __syncthreads();
    __threadfence();
}

__global__ __launch_bounds__(NTHR, 1)
void rbb_fused(const float* __restrict__ x, float* __restrict__ out)
{
    const int tid  = threadIdx.x;
    const int bid  = blockIdx.x;
    const int gtid = bid * NTHR + tid;

    // ---------------- P0: zero output + nz, decode + compact -----------------
    for (int i = gtid; i < (NCELL * 5) / 4; i += GTOT)
        ((float4*)out)[i] = make_float4(0.f, 0.f, 0.f, 0.f);
    if (gtid < MAXNW) g_nz[gtid] = 0ull;

    for (int c = gtid; c < NCELL; c += GTOT) {
        float s = x[c];
        if (s > 0.9f) {
            int   p  = c / PDIM;
            int   q  = c - p * PDIM;
            float ii = (float)p * XPSF;
            float jj = (float)q * YPSF;
            float v1 = x[1 * NCELL + c];
            float v2 = x[2 * NCELL + c];
            float v3 = x[3 * NCELL + c];
            float v4 = x[4 * NCELL + c];
            float bx1 = v1 * WIDTHF  + ii;
            float by1 = v2 * HEIGHTF + jj;
            float bx2 = (v3 - v1) * WIDTHF  + ii;
            float by2 = (v4 - v2) * HEIGHTF + jj;
            int k = atomicAdd(&g_cnt, 1);
            g_cscore[k] = s;
            g_cbox[k]   = make_float4(bx1, by1, bx2, by2);
            g_corig[k]  = c;
        }
    }
    grid_barrier(1 * NBLK);

    const int M = *(volatile int*)&g_cnt;

    // ---------------- P1: stable rank (score desc, orig asc) ----------------
    {
        float* sc = (float*)dyn_smem;               // [M]
        int*   so = (int*)(dyn_smem + NCELL * 4);   // [M]
        for (int i = tid; i < M; i += NTHR) {
            sc[i] = g_cscore[i];
            so[i] = g_corig[i];
        }
        __syncthreads();
        for (int k = tid * NBLK + bid; k < M; k += GTOT) {
            float sk = sc[k];
            int   ok = so[k];
            int   r  = 0;
            for (int j = 0; j < M; j++) {
                float sj = sc[j];
                r += (sj > sk) || (sj == sk && so[j] < ok);
            }
            g_sbox[r]   = g_cbox[k];
            g_sscore[r] = sk;
        }
    }
    grid_barrier(2 * NBLK);

    // ---------------- P2: per-block active compaction + bit-matrix -----------
    __shared__ unsigned s_bm[288];       // active bitmap, 32-bit granules
    __shared__ int      s_pfx[289];      // exclusive prefix popcounts
    float4* abox  = (float4*)dyn_smem;               // [A]
    int*    arank = (int*)(dyn_smem + 147456);       // [A]
    {
        const int n32 = (M + 31) >> 5;
        // build bitmap via ballot (deterministic, ordered)
        for (int t = 0; t < NCELL; t += NTHR) {
            int r = t + tid;
            if (r - (tid & 31) < M) {        // warp has at least one r < M
                bool act = false;
                if (r < M) {
                    float4 b = g_sbox[r];
                    act = (b.z > b.x) && (b.w > b.y);
                }
                unsigned bal = __ballot_sync(0xFFFFFFFFu, act);
                if ((tid & 31) == 0) s_bm[r >> 5] = bal;
            }
        }
        __syncthreads();
        if (tid == 0) {
            int acc = 0;
            for (int i = 0; i < n32; i++) { s_pfx[i] = acc; acc += __popc(s_bm[i]); }
            s_pfx[n32] = acc;
        }
        __syncthreads();
        // compact actives in rank order
        for (int r = tid; r < M; r += NTHR) {
            unsigned w = s_bm[r >> 5];
            if ((w >> (r & 31)) & 1u) {
                int pos = s_pfx[r >> 5] + __popc(w & ((1u << (r & 31)) - 1u));
                abox[pos]  = g_sbox[r];
                arank[pos] = r;
            }
        }
        __syncthreads();
    }
    const int n32M = (M + 31) >> 5;
    const int A    = s_pfx[n32M];
    const int na   = (A + 63) >> 6;

    // suppression bit-matrix over actives (grid-strided items)
    {
        const int total = A * na;
        for (int it = gtid; it < total; it += GTOT) {
            int i = it / na;
            int w = it - i * na;
            if (w < (i >> 6)) continue;            // never read by the scan

            float4 bi = abox[i];
            float  ai = (bi.z - bi.x) * (bi.w - bi.y);

            int base = w << 6;
            int nb   = min(64, A - base);
            unsigned long long bits = 0;
            for (int b = 0; b < nb; b++) {
                int j = base + b;
                if (j > i) {
                    float4 bj = abox[j];
                    float  aj = (bj.z - bj.x) * (bj.w - bj.y);
                    float iw = fmaxf(fminf(bi.z, bj.z) - fmaxf(bi.x, bj.x), 0.0f);
                    float ih = fmaxf(fminf(bi.w, bj.w) - fmaxf(bi.y, bj.y), 0.0f);
                    float inter = iw * ih;
                    float iou = inter / (ai + aj - inter + 1e-9f);
                    if (iou > 0.5f) bits |= (1ull << b);
                }
            }
            g_sup[it] = bits;
            if (bits)
                atomicOr(&g_nz[i >> 6], 1ull << (i & 63));
        }
    }
    grid_barrier(3 * NBLK);

    // ---------------- P4: block 0: sparse scan + map + scatter ---------------
    if (bid == 0) {
        __shared__ unsigned long long skeepA[MAXNW];
        __shared__ unsigned long long skeepR[MAXNW];
        __shared__ unsigned long long snz[MAXNW];
        unsigned long long* ssup = (unsigned long long*)dyn_smem; // overlays abox

        const bool fast = (A * na) <= SSUP_WORDS;
        if (fast) {
            for (int i = tid; i < A * na; i += NTHR)
                ssup[i] = g_sup[i];
        }
        const int nwR = (M + 63) >> 6;
        if (tid < MAXNW) {
            if (tid < na) {
                int nb = A - (tid << 6);
                skeepA[tid] = (nb >= 64) ? ~0ull : ((1ull << nb) - 1ull);
                snz[tid]    = g_nz[tid];
            }
            if (tid < nwR) {
                int nb = M - (tid << 6);
                skeepR[tid] = (nb >= 64) ? ~0ull : ((1ull << nb) - 1ull);
            }
        }
        __syncthreads();

        if (tid < 32 && A > 0) {
            const int lane = tid;
            for (int c = 0; c < na; c++) {
                const int base = c << 6;

                // resolve: walk only kept rows that suppress somebody
                if (lane == 0) {
                    unsigned long long kw  = skeepA[c];
                    unsigned long long rem = kw & snz[c];
                    while (rem) {
                        int b = __ffsll((long long)rem) - 1;
                        unsigned long long s = fast
                            ? ssup[(size_t)(base + b) * na + c]
                            : g_sup[(size_t)(base + b) * na + c];
                        kw  &= ~s;          // bits in s are strictly > b
                        rem &= ~s;
                        rem &= rem - 1;     // clear processed (lowest) bit
                    }
                    skeepA[c] = kw;
                }
                __syncwarp();

                // apply: suppressing survivors hit future words
                const unsigned long long kwnz = skeepA[c] & snz[c];
                if (kwnz) {
                    for (int w = c + 1 + lane; w < na; w += 32) {
                        unsigned long long acc = 0, t = kwnz;
                        while (t) {
                            int b = __ffsll((long long)t) - 1;
                            t &= t - 1;
                            acc |= fast ? ssup[(size_t)(base + b) * na + w]
                                        : g_sup[(size_t)(base + b) * na + w];
                        }
                        skeepA[w] &= ~acc;
                    }
                }
                __syncwarp();
            }
        }
        __syncthreads();

        // map suppressed actives back to sorted ranks
        for (int a = tid; a < A; a += NTHR) {
            if (!((skeepA[a >> 6] >> (a & 63)) & 1ull)) {
                int r = arank[a];
                atomicAnd(&skeepR[r >> 6], ~(1ull << (r & 63)));
            }
        }
        __syncthreads();

        // scatter kept rows (output zeroed in P0)
        for (int r = tid; r < M; r += NTHR) {
            if ((skeepR[r >> 6] >> (r & 63)) & 1ull) {
                float4 b = g_sbox[r];
                out[r * 5 + 0] = g_sscore[r];
                out[r * 5 + 1] = b.x;
                out[r * 5 + 2] = b.y;
                out[r * 5 + 3] = b.z - b.x;
                out[r * 5 + 4] = b.w - b.y;
            }
        }
    }

    // ---------------- final: reset counters for next replay ------------------
    __syncthreads();
    if (bid != 0) {
        if (tid == 0) { __threadfence(); atomicAdd(&g_bar, 1); }
        return;
    }
    if (tid == 0) {
        // wait for every other block to post its final arrive, then reset
        while (*(volatile int*)&g_bar < 3 * NBLK + (NBLK - 1)) { }
        g_cnt = 0;
        g_bar = 0;
        __threadfence();
    }
}

// ---------------------------------------------------------------------------
extern "C" void kernel_launch(void* const* d_in, const int* in_sizes, int n_in,
                              void* d_out, int out_size)
{
    (void)in_sizes; (void)n_in; (void)out_size;
    const float* x   = (const float*)d_in[0];
    float*       out = (float*)d_out;

    cudaFuncSetAttribute(rbb_fused,
                         cudaFuncAttributeMaxDynamicSharedMemorySize,
                         184320);

    rbb_fused<<<NBLK, NTHR, 184320>>>(x, out);
}

// round 11
// speedup vs baseline: 11.9847x; 2.3591x over previous
#include <cuda_runtime.h>

// ReduceBoundingBoxes: decode + threshold + stable sort + greedy NMS.
// SINGLE persistent kernel, 18 blocks x 1024 threads, 3 software grid barriers.
//   P0: zero output + nz, decode + warp-aggregated compaction
//   B1
//   P1: stable rank via packed u64 keys, warp-per-k, lane-parallel j
//   B2
//   P2: per-block active compaction (ballot bitmap) + bit-matrix over actives
//   B3
//   P4: block 0: sparse chunked greedy scan + map back + scatter
//   end: block 0 waits for all, resets counters for next graph replay.

#define NCELL   9216
#define PDIM    96
#define WIDTHF  3072.0f
#define HEIGHTF 2304.0f
#define XPSF    32.0f    // multiplies ROW index (P dim)
#define YPSF    24.0f    // multiplies COL index (Q dim)
#define MAXNW   144      // ceil(9216/64)
#define NBLK    18
#define NTHR    1024
#define GTOT    (NBLK * NTHR)
#define SSUP_WORDS 18432          // 147456 B overlay for scan fast path

typedef unsigned long long u64;

// -------- global scratch (static device memory) ----------------------------
__device__ int    g_cnt;    // valid-box count; reset at end of every run
__device__ int    g_bar;    // grid-barrier arrivals; reset at end of every run
__device__ float  g_cscore[NCELL];
__device__ float4 g_cbox[NCELL];
__device__ int    g_corig[NCELL];
__device__ float  g_sscore[NCELL];
__device__ float4 g_sbox[NCELL];
__device__ u64    g_nz[MAXNW];
__device__ u64    g_sup[(size_t)NCELL * MAXNW];

// dynamic SMEM layout (184320 B):
//   [0      , 147456): P1 skey[M] u64 | P2 abox[A] float4 | P4 ssup overlay
//   [147456 , 184320): P2/P4 arank[A] int
extern __shared__ unsigned char dyn_smem[];

__device__ __forceinline__ void grid_barrier(int target)
{
    __syncthreads();
    if (threadIdx.x == 0) {
        __threadfence();
        atomicAdd(&g_bar, 1);
        while (*(volatile int*)&g_bar < target) { }
    }
    __syncthreads();
    __threadfence();
}

__global__ __launch_bounds__(NTHR, 1)
void rbb_fused(const float* __restrict__ x, float* __restrict__ out)
{
    const int tid  = threadIdx.x;
    const int bid  = blockIdx.x;
    const int gtid = bid * NTHR + tid;
    const int wid  = tid >> 5;
    const int lane = tid & 31;

    // ---------------- P0: zero output + nz, decode + compact -----------------
    for (int i = gtid; i < (NCELL * 5) / 4; i += GTOT)
        ((float4*)out)[i] = make_float4(0.f, 0.f, 0.f, 0.f);
    if (gtid < MAXNW) g_nz[gtid] = 0ull;

    // NCELL is a multiple of 32 and gtid is warp-contiguous, so every warp
    // executes this loop a warp-uniform number of times.
    for (int c = gtid; c < NCELL; c += GTOT) {
        float s = x[c];
        bool valid = s > 0.9f;
        unsigned mask = __ballot_sync(0xFFFFFFFFu, valid);
        if (mask) {
            int leader = __ffs(mask) - 1;
            int base = 0;
            if (lane == leader) base = atomicAdd(&g_cnt, __popc(mask));
            base = __shfl_sync(0xFFFFFFFFu, base, leader);
            if (valid) {
                int   k  = base + __popc(mask & ((1u << lane) - 1u));
                int   p  = c / PDIM;
                int   q  = c - p * PDIM;
                float ii = (float)p * XPSF;
                float jj = (float)q * YPSF;
                float v1 = x[1 * NCELL + c];
                float v2 = x[2 * NCELL + c];
                float v3 = x[3 * NCELL + c];
                float v4 = x[4 * NCELL + c];
                float bx1 = v1 * WIDTHF  + ii;
                float by1 = v2 * HEIGHTF + jj;
                float bx2 = (v3 - v1) * WIDTHF  + ii;
                float by2 = (v4 - v2) * HEIGHTF + jj;
                g_cscore[k] = s;
                g_cbox[k]   = make_float4(bx1, by1, bx2, by2);
                g_corig[k]  = c;
            }
        }
    }
    grid_barrier(1 * NBLK);

    const int M = *(volatile int*)&g_cnt;

    // ---------------- P1: stable rank via packed u64 keys --------------------
    // key = (score_bits << 32) | ~orig. Scores are positive floats, so the
    // uint bit pattern is order-isomorphic to the value. key_j > key_k <=>
    // s_j > s_k, or s_j == s_k and orig_j < orig_k. Keys unique (orig
    // distinct) -> rank is a permutation.
    {
        u64* skey = (u64*)dyn_smem;                 // [M]
        for (int i = tid; i < M; i += NTHR)
            skey[i] = ((u64)__float_as_uint(g_cscore[i]) << 32)
                    | (u64)(0xFFFFFFFFu - (unsigned)g_corig[i]);
        __syncthreads();

        // warp-per-k, j parallel across lanes, warp sum reduction
        for (int k = bid * 32 + wid; k < M; k += NBLK * 32) {
            u64 mykey = skey[k];
            int r = 0;
            for (int j = lane; j < M; j += 32)
                r += (skey[j] > mykey);
            r = __reduce_add_sync(0xFFFFFFFFu, r);
            if (lane == 0) {
                g_sbox[r]   = g_cbox[k];
                g_sscore[r] = g_cscore[k];
            }
        }
    }
    grid_barrier(2 * NBLK);

    // ---------------- P2: per-block active compaction + bit-matrix -----------
    __shared__ unsigned s_bm[288];       // active bitmap, 32-bit granules
    __shared__ int      s_pfx[289];      // exclusive prefix popcounts
    float4* abox  = (float4*)dyn_smem;               // [A]
    int*    arank = (int*)(dyn_smem + 147456);       // [A]
    {
        const int n32 = (M + 31) >> 5;
        for (int t = 0; t < NCELL; t += NTHR) {
            int r = t + tid;
            if (r - lane < M) {                 // warp has at least one r < M
                bool act = false;
                if (r < M) {
                    float4 b = g_sbox[r];
                    act = (b.z > b.x) && (b.w > b.y);
                }
                unsigned bal = __ballot_sync(0xFFFFFFFFu, act);
                if (lane == 0) s_bm[r >> 5] = bal;
            }
        }
        __syncthreads();
        if (tid == 0) {
            int acc = 0;
            for (int i = 0; i < n32; i++) { s_pfx[i] = acc; acc += __popc(s_bm[i]); }
            s_pfx[n32] = acc;
        }
        __syncthreads();
        for (int r = tid; r < M; r += NTHR) {
            unsigned w = s_bm[r >> 5];
            if ((w >> (r & 31)) & 1u) {
                int pos = s_pfx[r >> 5] + __popc(w & ((1u << (r & 31)) - 1u));
                abox[pos]  = g_sbox[r];
                arank[pos] = r;
            }
        }
        __syncthreads();
    }
    const int n32M = (M + 31) >> 5;
    const int A    = s_pfx[n32M];
    const int na   = (A + 63) >> 6;

    // suppression bit-matrix over actives (grid-strided items)
    {
        const int total = A * na;
        for (int it = gtid; it < total; it += GTOT) {
            int i = it / na;
            int w = it - i * na;
            if (w < (i >> 6)) continue;            // never read by the scan

            float4 bi = abox[i];
            float  ai = (bi.z - bi.x) * (bi.w - bi.y);

            int base = w << 6;
            int nb   = min(64, A - base);
            u64 bits = 0;
            for (int b = 0; b < nb; b++) {
                int j = base + b;
                if (j > i) {
                    float4 bj = abox[j];
                    float  aj = (bj.z - bj.x) * (bj.w - bj.y);
                    float iw = fmaxf(fminf(bi.z, bj.z) - fmaxf(bi.x, bj.x), 0.0f);
                    float ih = fmaxf(fminf(bi.w, bj.w) - fmaxf(bi.y, bj.y), 0.0f);
                    float inter = iw * ih;
                    float iou = inter / (ai + aj - inter + 1e-9f);
                    if (iou > 0.5f) bits |= (1ull << b);
                }
            }
            g_sup[it] = bits;
            if (bits)
                atomicOr(&g_nz[i >> 6], 1ull << (i & 63));
        }
    }
    grid_barrier(3 * NBLK);

    // ---------------- P4: block 0: sparse scan + map + scatter ---------------
    if (bid == 0) {
        __shared__ u64 skeepA[MAXNW];
        __shared__ u64 skeepR[MAXNW];
        __shared__ u64 snz[MAXNW];
        u64* ssup = (u64*)dyn_smem;                 // overlays abox

        const bool fast = (A * na) <= SSUP_WORDS;
        if (fast) {
            for (int i = tid; i < A * na; i += NTHR)
                ssup[i] = g_sup[i];
        }
        const int nwR = (M + 63) >> 6;
        if (tid < MAXNW) {
            if (tid < na) {
                int nb = A - (tid << 6);
                skeepA[tid] = (nb >= 64) ? ~0ull : ((1ull << nb) - 1ull);
                snz[tid]    = g_nz[tid];
            }
            if (tid < nwR) {
                int nb = M - (tid << 6);
                skeepR[tid] = (nb >= 64) ? ~0ull : ((1ull << nb) - 1ull);
            }
        }
        __syncthreads();

        if (tid < 32 && A > 0) {
            const int ln = tid;
            for (int c = 0; c < na; c++) {
                const int base = c << 6;

                // resolve: walk only kept rows that suppress somebody
                if (ln == 0) {
                    u64 kw  = skeepA[c];
                    u64 rem = kw & snz[c];
                    while (rem) {
                        int b = __ffsll((long long)rem) - 1;
                        u64 s = fast ? ssup[(size_t)(base + b) * na + c]
                                     : g_sup[(size_t)(base + b) * na + c];
                        kw  &= ~s;          // bits in s are strictly > b
                        rem &= ~s;
                        rem &= rem - 1;     // clear processed (lowest) bit
                    }
                    skeepA[c] = kw;
                }
                __syncwarp();

                // apply: suppressing survivors hit future words
                const u64 kwnz = skeepA[c] & snz[c];
                if (kwnz) {
                    for (int w = c + 1 + ln; w < na; w += 32) {
                        u64 acc = 0, t = kwnz;
                        while (t) {
                            int b = __ffsll((long long)t) - 1;
                            t &= t - 1;
                            acc |= fast ? ssup[(size_t)(base + b) * na + w]
                                        : g_sup[(size_t)(base + b) * na + w];
                        }
                        skeepA[w] &= ~acc;
                    }
                }
                __syncwarp();
            }
        }
        __syncthreads();

        // map suppressed actives back to sorted ranks
        for (int a = tid; a < A; a += NTHR) {
            if (!((skeepA[a >> 6] >> (a & 63)) & 1ull)) {
                int r = arank[a];
                atomicAnd(&skeepR[r >> 6], ~(1ull << (r & 63)));
            }
        }
        __syncthreads();

        // scatter kept rows (output zeroed in P0)
        for (int r = tid; r < M; r += NTHR) {
            if ((skeepR[r >> 6] >> (r & 63)) & 1ull) {
                float4 b = g_sbox[r];
                out[r * 5 + 0] = g_sscore[r];
                out[r * 5 + 1] = b.x;
                out[r * 5 + 2] = b.y;
                out[r * 5 + 3] = b.z - b.x;
                out[r * 5 + 4] = b.w - b.y;
            }
        }
    }

    // ---------------- final: reset counters for next replay ------------------
    __syncthreads();
    if (bid != 0) {
        if (tid == 0) { __threadfence(); atomicAdd(&g_bar, 1); }
        return;
    }
    if (tid == 0) {
        while (*(volatile int*)&g_bar < 3 * NBLK + (NBLK - 1)) { }
        g_cnt = 0;
        g_bar = 0;
        __threadfence();
    }
}

// ---------------------------------------------------------------------------
extern "C" void kernel_launch(void* const* d_in, const int* in_sizes, int n_in,
                              void* d_out, int out_size)
{
    (void)in_sizes; (void)n_in; (void)out_size;
    const float* x   = (const float*)d_in[0];
    float*       out = (float*)d_out;

    cudaFuncSetAttribute(rbb_fused,
                         cudaFuncAttributeMaxDynamicSharedMemorySize,
                         184320);

    rbb_fused<<<NBLK, NTHR, 184320>>>(x, out);
}

// round 12
// speedup vs baseline: 12.0707x; 1.0072x over previous
#include <cuda_runtime.h>

// ReduceBoundingBoxes: decode + threshold + stable sort + greedy NMS.
// SINGLE persistent kernel, 18 blocks x 1024 threads, 3 software grid barriers.
//   P0: zero output + nz, decode + warp-aggregated compaction
//   B1
//   P1: stable rank via packed u64 keys, warp-per-k, lane-parallel j
//   B2
//   P2: per-block active compaction (ballot bitmap) + bit-matrix over actives
//       (items strided BLOCK-FIRST so small totals still use all SMs)
//   B3
//   P4: block 0: sparse chunked greedy scan + map back + scatter
//   end: block 0 waits for all, resets counters for next graph replay.

#define NCELL   9216
#define PDIM    96
#define WIDTHF  3072.0f
#define HEIGHTF 2304.0f
#define XPSF    32.0f    // multiplies ROW index (P dim)
#define YPSF    24.0f    // multiplies COL index (Q dim)
#define MAXNW   144      // ceil(9216/64)
#define NBLK    18
#define NTHR    1024
#define GTOT    (NBLK * NTHR)
#define SSUP_WORDS 18432          // 147456 B overlay for scan fast path

typedef unsigned long long u64;

// -------- global scratch (static device memory) ----------------------------
__device__ int    g_cnt;    // valid-box count; reset at end of every run
__device__ int    g_bar;    // grid-barrier arrivals; reset at end of every run
__device__ float  g_cscore[NCELL];
__device__ float4 g_cbox[NCELL];
__device__ int    g_corig[NCELL];
__device__ float  g_sscore[NCELL];
__device__ float4 g_sbox[NCELL];
__device__ u64    g_nz[MAXNW];
__device__ u64    g_sup[(size_t)NCELL * MAXNW];

// dynamic SMEM layout (184320 B):
//   [0      , 147456): P1 skey[M] u64 | P2 abox[A] float4 | P4 ssup overlay
//   [147456 , 184320): P2/P4 arank[A] int
extern __shared__ unsigned char dyn_smem[];

__device__ __forceinline__ void grid_barrier(int target)
{
    __syncthreads();
    if (threadIdx.x == 0) {
        __threadfence();
        atomicAdd(&g_bar, 1);
        while (*(volatile int*)&g_bar < target) { }
    }
    __syncthreads();
    __threadfence();
}

__global__ __launch_bounds__(NTHR, 1)
void rbb_fused(const float* __restrict__ x, float* __restrict__ out)
{
    const int tid  = threadIdx.x;
    const int bid  = blockIdx.x;
    const int gtid = bid * NTHR + tid;
    const int wid  = tid >> 5;
    const int lane = tid & 31;

    // ---------------- P0: zero output + nz, decode + compact -----------------
    for (int i = gtid; i < (NCELL * 5) / 4; i += GTOT)
        ((float4*)out)[i] = make_float4(0.f, 0.f, 0.f, 0.f);
    if (gtid < MAXNW) g_nz[gtid] = 0ull;

    // NCELL is a multiple of 32 and gtid is warp-contiguous, so every warp
    // executes this loop a warp-uniform number of times.
    for (int c = gtid; c < NCELL; c += GTOT) {
        float s = x[c];
        bool valid = s > 0.9f;
        unsigned mask = __ballot_sync(0xFFFFFFFFu, valid);
        if (mask) {
            int leader = __ffs(mask) - 1;
            int base = 0;
            if (lane == leader) base = atomicAdd(&g_cnt, __popc(mask));
            base = __shfl_sync(0xFFFFFFFFu, base, leader);
            if (valid) {
                int   k  = base + __popc(mask & ((1u << lane) - 1u));
                int   p  = c / PDIM;
                int   q  = c - p * PDIM;
                float ii = (float)p * XPSF;
                float jj = (float)q * YPSF;
                float v1 = x[1 * NCELL + c];
                float v2 = x[2 * NCELL + c];
                float v3 = x[3 * NCELL + c];
                float v4 = x[4 * NCELL + c];
                float bx1 = v1 * WIDTHF  + ii;
                float by1 = v2 * HEIGHTF + jj;
                float bx2 = (v3 - v1) * WIDTHF  + ii;
                float by2 = (v4 - v2) * HEIGHTF + jj;
                g_cscore[k] = s;
                g_cbox[k]   = make_float4(bx1, by1, bx2, by2);
                g_corig[k]  = c;
            }
        }
    }
    grid_barrier(1 * NBLK);

    const int M = *(volatile int*)&g_cnt;

    // ---------------- P1: stable rank via packed u64 keys --------------------
    // key = (score_bits << 32) | ~orig. Scores are positive floats, so the
    // uint bit pattern is order-isomorphic to the value. key_j > key_k <=>
    // s_j > s_k, or s_j == s_k and orig_j < orig_k. Keys unique (orig
    // distinct) -> rank is a permutation.
    {
        u64* skey = (u64*)dyn_smem;                 // [M]
        for (int i = tid; i < M; i += NTHR)
            skey[i] = ((u64)__float_as_uint(g_cscore[i]) << 32)
                    | (u64)(0xFFFFFFFFu - (unsigned)g_corig[i]);
        __syncthreads();

        // warp-per-k, j parallel across lanes, warp sum reduction
        for (int k = bid * 32 + wid; k < M; k += NBLK * 32) {
            u64 mykey = skey[k];
            int r = 0;
            for (int j = lane; j < M; j += 32)
                r += (skey[j] > mykey);
            r = __reduce_add_sync(0xFFFFFFFFu, r);
            if (lane == 0) {
                g_sbox[r]   = g_cbox[k];
                g_sscore[r] = g_cscore[k];
            }
        }
    }
    grid_barrier(2 * NBLK);

    // ---------------- P2: per-block active compaction + bit-matrix -----------
    __shared__ unsigned s_bm[288];       // active bitmap, 32-bit granules
    __shared__ int      s_pfx[289];      // exclusive prefix popcounts
    float4* abox  = (float4*)dyn_smem;               // [A]
    int*    arank = (int*)(dyn_smem + 147456);       // [A]
    {
        const int n32 = (M + 31) >> 5;
        for (int t = 0; t < NCELL; t += NTHR) {
            int r = t + tid;
            if (r - lane < M) {                 // warp has at least one r < M
                bool act = false;
                if (r < M) {
                    float4 b = g_sbox[r];
                    act = (b.z > b.x) && (b.w > b.y);
                }
                unsigned bal = __ballot_sync(0xFFFFFFFFu, act);
                if (lane == 0) s_bm[r >> 5] = bal;
            }
        }
        __syncthreads();
        if (tid == 0) {
            int acc = 0;
            for (int i = 0; i < n32; i++) { s_pfx[i] = acc; acc += __popc(s_bm[i]); }
            s_pfx[n32] = acc;
        }
        __syncthreads();
        for (int r = tid; r < M; r += NTHR) {
            unsigned w = s_bm[r >> 5];
            if ((w >> (r & 31)) & 1u) {
                int pos = s_pfx[r >> 5] + __popc(w & ((1u << (r & 31)) - 1u));
                abox[pos]  = g_sbox[r];
                arank[pos] = r;
            }
        }
        __syncthreads();
    }
    const int n32M = (M + 31) >> 5;
    const int A    = s_pfx[n32M];
    const int na   = (A + 63) >> 6;

    // suppression bit-matrix over actives.
    // BLOCK-FIRST striding (it = tid*NBLK + bid): for small totals (~A*na ~
    // 1k items) the work spreads across all NBLK blocks instead of landing
    // entirely in block 0 (the gtid-strided form serialized this phase onto
    // one SM).
    {
        const int total = A * na;
        for (int it = tid * NBLK + bid; it < total; it += GTOT) {
            int i = it / na;
            int w = it - i * na;
            if (w < (i >> 6)) continue;            // never read by the scan

            float4 bi = abox[i];
            float  ai = (bi.z - bi.x) * (bi.w - bi.y);

            int base = w << 6;
            int nb   = min(64, A - base);
            u64 bits = 0;
            for (int b = 0; b < nb; b++) {
                int j = base + b;
                if (j > i) {
                    float4 bj = abox[j];
                    float  aj = (bj.z - bj.x) * (bj.w - bj.y);
                    float iw = fmaxf(fminf(bi.z, bj.z) - fmaxf(bi.x, bj.x), 0.0f);
                    float ih = fmaxf(fminf(bi.w, bj.w) - fmaxf(bi.y, bj.y), 0.0f);
                    float inter = iw * ih;
                    float iou = inter / (ai + aj - inter + 1e-9f);
                    if (iou > 0.5f) bits |= (1ull << b);
                }
            }
            g_sup[it] = bits;
            if (bits)
                atomicOr(&g_nz[i >> 6], 1ull << (i & 63));
        }
    }
    grid_barrier(3 * NBLK);

    // ---------------- P4: block 0: sparse scan + map + scatter ---------------
    if (bid == 0) {
        __shared__ u64 skeepA[MAXNW];
        __shared__ u64 skeepR[MAXNW];
        __shared__ u64 snz[MAXNW];
        u64* ssup = (u64*)dyn_smem;                 // overlays abox

        const bool fast = (A * na) <= SSUP_WORDS;
        if (fast) {
            for (int i = tid; i < A * na; i += NTHR)
                ssup[i] = g_sup[i];
        }
        const int nwR = (M + 63) >> 6;
        if (tid < MAXNW) {
            if (tid < na) {
                int nb = A - (tid << 6);
                skeepA[tid] = (nb >= 64) ? ~0ull : ((1ull << nb) - 1ull);
                snz[tid]    = g_nz[tid];
            }
            if (tid < nwR) {
                int nb = M - (tid << 6);
                skeepR[tid] = (nb >= 64) ? ~0ull : ((1ull << nb) - 1ull);
            }
        }
        __syncthreads();

        if (tid < 32 && A > 0) {
            const int ln = tid;
            for (int c = 0; c < na; c++) {
                const int base = c << 6;

                // resolve: walk only kept rows that suppress somebody
                if (ln == 0) {
                    u64 kw  = skeepA[c];
                    u64 rem = kw & snz[c];
                    while (rem) {
                        int b = __ffsll((long long)rem) - 1;
                        u64 s = fast ? ssup[(size_t)(base + b) * na + c]
                                     : g_sup[(size_t)(base + b) * na + c];
                        kw  &= ~s;          // bits in s are strictly > b
                        rem &= ~s;
                        rem &= rem - 1;     // clear processed (lowest) bit
                    }
                    skeepA[c] = kw;
                }
                __syncwarp();

                // apply: suppressing survivors hit future words
                const u64 kwnz = skeepA[c] & snz[c];
                if (kwnz) {
                    for (int w = c + 1 + ln; w < na; w += 32) {
                        u64 acc = 0, t = kwnz;
                        while (t) {
                            int b = __ffsll((long long)t) - 1;
                            t &= t - 1;
                            acc |= fast ? ssup[(size_t)(base + b) * na + w]
                                        : g_sup[(size_t)(base + b) * na + w];
                        }
                        skeepA[w] &= ~acc;
                    }
                }
                __syncwarp();
            }
        }
        __syncthreads();

        // map suppressed actives back to sorted ranks
        for (int a = tid; a < A; a += NTHR) {
            if (!((skeepA[a >> 6] >> (a & 63)) & 1ull)) {
                int r = arank[a];
                atomicAnd(&skeepR[r >> 6], ~(1ull << (r & 63)));
            }
        }
        __syncthreads();

        // scatter kept rows (output zeroed in P0)
        for (int r = tid; r < M; r += NTHR) {
            if ((skeepR[r >> 6] >> (r & 63)) & 1ull) {
                float4 b = g_sbox[r];
                out[r * 5 + 0] = g_sscore[r];
                out[r * 5 + 1] = b.x;
                out[r * 5 + 2] = b.y;
                out[r * 5 + 3] = b.z - b.x;
                out[r * 5 + 4] = b.w - b.y;
            }
        }
    }

    // ---------------- final: reset counters for next replay ------------------
    __syncthreads();
    if (bid != 0) {
        if (tid == 0) { __threadfence(); atomicAdd(&g_bar, 1); }
        return;
    }
    if (tid == 0) {
        while (*(volatile int*)&g_bar < 3 * NBLK + (NBLK - 1)) { }
        g_cnt = 0;
        g_bar = 0;
        __threadfence();
    }
}

// ---------------------------------------------------------------------------
extern "C" void kernel_launch(void* const* d_in, const int* in_sizes, int n_in,
                              void* d_out, int out_size)
{
    (void)in_sizes; (void)n_in; (void)out_size;
    const float* x   = (const float*)d_in[0];
    float*       out = (float*)d_out;

    cudaFuncSetAttribute(rbb_fused,
                         cudaFuncAttributeMaxDynamicSharedMemorySize,
                         184320);

    rbb_fused<<<NBLK, NTHR, 184320>>>(x, out);
}

// round 13
// speedup vs baseline: 17.9588x; 1.4878x over previous
#include <cuda_runtime.h>

// ReduceBoundingBoxes: decode + threshold + stable sort + greedy NMS.
// SINGLE persistent kernel, 18 blocks x 1024 threads, TWO software grid
// barriers.
//   P0: zero output, decode + warp-aggregated compaction, act flag + count
//   B1
//   P1: stable rank via packed u64 keys (warp-per-k, lane-parallel j),
//       computing BOTH global rank r and active-rank ra in one pass ->
//       sorted arrays AND compacted active array, no extra phase.
//   B2  (blocks != 0 then arrive-and-exit)
//   P4: block 0 only: in-SMEM ballot-built suppression bit-matrix over
//       actives + sparse chunked greedy scan + map back + scatter.
//   end: block 0 waits for all arrivals, resets counters for next replay.

#define NCELL   9216
#define PDIM    96
#define WIDTHF  3072.0f
#define HEIGHTF 2304.0f
#define XPSF    32.0f    // multiplies ROW index (P dim)
#define YPSF    24.0f    // multiplies COL index (Q dim)
#define MAXNW   144      // ceil(9216/64)
#define NBLK    18
#define NTHR    1024
#define GTOT    (NBLK * NTHR)
#define DSMEM_BYTES 184320

typedef unsigned long long u64;

// -------- global scratch (static device memory) ----------------------------
__device__ int    g_cnt;    // valid-box count;  reset at end of every run
__device__ int    g_acnt;   // active-box count; reset at end of every run
__device__ int    g_bar;    // barrier arrivals; reset at end of every run
__device__ float  g_cscore[NCELL];
__device__ float4 g_cbox[NCELL];
__device__ int    g_corig[NCELL];
__device__ unsigned char g_cact[NCELL];
__device__ float  g_sscore[NCELL];
__device__ float4 g_sbox[NCELL];
__device__ float4 g_abox[NCELL];    // active boxes in rank order
__device__ int    g_amap[NCELL];    // active a -> global sorted rank r
__device__ u64    g_sup[(size_t)NCELL * MAXNW];   // fallback only (A large)

extern __shared__ unsigned char dyn_smem[];

__device__ __forceinline__ void grid_barrier(int target)
{
    __syncthreads();
    if (threadIdx.x == 0) {
        __threadfence();
        atomicAdd(&g_bar, 1);
        while (*(volatile int*)&g_bar < target) { }
    }
    __syncthreads();
    __threadfence();
}

__global__ __launch_bounds__(NTHR, 1)
void rbb_fused(const float* __restrict__ x, float* __restrict__ out)
{
    const int tid  = threadIdx.x;
    const int bid  = blockIdx.x;
    const int gtid = bid * NTHR + tid;
    const int wid  = tid >> 5;
    const int lane = tid & 31;

    // ---------------- P0: zero output, decode + compact + act ----------------
    for (int i = gtid; i < (NCELL * 5) / 4; i += GTOT)
        ((float4*)out)[i] = make_float4(0.f, 0.f, 0.f, 0.f);

    for (int c = gtid; c < NCELL; c += GTOT) {
        float s = x[c];
        bool valid = s > 0.9f;
        bool act = false;
        float bx1 = 0.f, by1 = 0.f, bx2 = 0.f, by2 = 0.f;
        if (valid) {
            int   p  = c / PDIM;
            int   q  = c - p * PDIM;
            float ii = (float)p * XPSF;
            float jj = (float)q * YPSF;
            float v1 = x[1 * NCELL + c];
            float v2 = x[2 * NCELL + c];
            float v3 = x[3 * NCELL + c];
            float v4 = x[4 * NCELL + c];
            bx1 = v1 * WIDTHF  + ii;
            by1 = v2 * HEIGHTF + jj;
            bx2 = (v3 - v1) * WIDTHF  + ii;
            by2 = (v4 - v2) * HEIGHTF + jj;
            act = (bx2 > bx1) && (by2 > by1);
        }
        unsigned vmask = __ballot_sync(0xFFFFFFFFu, valid);
        unsigned amask = __ballot_sync(0xFFFFFFFFu, act);
        if (vmask) {
            int leader = __ffs(vmask) - 1;
            int base = 0;
            if (lane == leader) {
                base = atomicAdd(&g_cnt, __popc(vmask));
                if (amask) atomicAdd(&g_acnt, __popc(amask));
            }
            base = __shfl_sync(0xFFFFFFFFu, base, leader);
            if (valid) {
                int k = base + __popc(vmask & ((1u << lane) - 1u));
                g_cscore[k] = s;
                g_cbox[k]   = make_float4(bx1, by1, bx2, by2);
                g_corig[k]  = c;
                g_cact[k]   = act ? 1 : 0;
            }
        }
    }
    grid_barrier(1 * NBLK);

    const int M = *(volatile int*)&g_cnt;
    const int A = *(volatile int*)&g_acnt;

    // ---------------- P1: rank (global + active) via packed u64 keys ---------
    // key = (score_bits << 32) | ~orig: order-isomorphic, unique.
    {
        u64*      skey  = (u64*)dyn_smem;                    // [M]
        unsigned* sactw = (unsigned*)(dyn_smem + 73728);     // [ceil(M/32)]

        for (int i = tid; i < M; i += NTHR)
            skey[i] = ((u64)__float_as_uint(g_cscore[i]) << 32)
                    | (u64)(0xFFFFFFFFu - (unsigned)g_corig[i]);
        // act bitmap (warp-uniform loop; NTHR and strides multiples of 32)
        for (int t = 0; t < NCELL; t += NTHR) {
            int i = t + tid;
            if (i - lane < M) {
                bool a = (i < M) && (g_cact[i] != 0);
                unsigned bal = __ballot_sync(0xFFFFFFFFu, a);
                if (lane == 0) sactw[i >> 5] = bal;
            }
        }
        __syncthreads();

        const int nit = (M + 31) >> 5;
        for (int k = bid * 32 + wid; k < M; k += NBLK * 32) {
            u64 mykey = skey[k];
            int r = 0, ra = 0;
            for (int it = 0; it < nit; it++) {
                int j = it * 32 + lane;
                if (j < M) {
                    int gt = (skey[j] > mykey);
                    r  += gt;
                    ra += gt & (int)((sactw[it] >> lane) & 1u);
                }
            }
            r  = __reduce_add_sync(0xFFFFFFFFu, r);
            ra = __reduce_add_sync(0xFFFFFFFFu, ra);
            if (lane == 0) {
                float4 bk = g_cbox[k];
                g_sbox[r]   = bk;
                g_sscore[r] = g_cscore[k];
                if (g_cact[k]) {
                    g_abox[ra] = bk;
                    g_amap[ra] = r;
                }
            }
        }
    }
    grid_barrier(2 * NBLK);

    // blocks != 0: arrive and exit (frees SMs; block 0 does the tail alone)
    if (bid != 0) {
        __syncthreads();
        if (tid == 0) { __threadfence(); atomicAdd(&g_bar, 1); }
        return;
    }

    // ---------------- P4 (block 0): in-SMEM matrix + scan + scatter ----------
    {
        __shared__ u64 skeepA[MAXNW];
        __shared__ u64 skeepR[MAXNW];
        __shared__ u64 snz[MAXNW];

        const int na = (A + 63) >> 6;
        // SMEM layout: sabox [0,16A) | samap [16A,20A) | ssup [align8(20A),..)
        float4* sabox = (float4*)dyn_smem;
        int*    samap = (int*)(dyn_smem + (size_t)A * 16);
        size_t  supoff = ((size_t)A * 20 + 7) & ~(size_t)7;
        u64*    ssup  = (u64*)(dyn_smem + supoff);
        const bool fast = (supoff + (size_t)A * na * 8) <= DSMEM_BYTES;

        for (int a = tid; a < A; a += NTHR) {
            sabox[a] = g_abox[a];
            samap[a] = g_amap[a];
        }
        if (tid < MAXNW) {
            snz[tid] = 0ull;
            if (tid < na) {
                int nb = A - (tid << 6);
                skeepA[tid] = (nb >= 64) ? ~0ull : ((1ull << nb) - 1ull);
            }
            int nwR = (M + 63) >> 6;
            if (tid < nwR) {
                int nb = M - (tid << 6);
                skeepR[tid] = (nb >= 64) ? ~0ull : ((1ull << nb) - 1ull);
            }
        }
        __syncthreads();

        // build suppression bit-matrix via warp ballots (warp-per-row)
        for (int i = wid; i < A; i += 32) {
            float4 bi = sabox[i];
            float  ai = (bi.z - bi.x) * (bi.w - bi.y);
            u64 rowor = 0;
            for (int w = (i >> 6); w < na; w++) {
                int j1 = (w << 6) + lane;
                int j2 = j1 + 32;
                bool p1 = false, p2 = false;
                if (j1 > i && j1 < A) {
                    float4 bj = sabox[j1];
                    float  aj = (bj.z - bj.x) * (bj.w - bj.y);
                    float iw = fmaxf(fminf(bi.z, bj.z) - fmaxf(bi.x, bj.x), 0.0f);
                    float ih = fmaxf(fminf(bi.w, bj.w) - fmaxf(bi.y, bj.y), 0.0f);
                    float inter = iw * ih;
                    p1 = inter / (ai + aj - inter + 1e-9f) > 0.5f;
                }
                if (j2 > i && j2 < A) {
                    float4 bj = sabox[j2];
                    float  aj = (bj.z - bj.x) * (bj.w - bj.y);
                    float iw = fmaxf(fminf(bi.z, bj.z) - fmaxf(bi.x, bj.x), 0.0f);
                    float ih = fmaxf(fminf(bi.w, bj.w) - fmaxf(bi.y, bj.y), 0.0f);
                    float inter = iw * ih;
                    p2 = inter / (ai + aj - inter + 1e-9f) > 0.5f;
                }
                unsigned lo = __ballot_sync(0xFFFFFFFFu, p1);
                unsigned hi = __ballot_sync(0xFFFFFFFFu, p2);
                u64 bits = (u64)lo | ((u64)hi << 32);
                if (lane == 0) {
                    if (fast) ssup[(size_t)i * na + w] = bits;
                    else      g_sup[(size_t)i * na + w] = bits;
                }
                rowor |= bits;
            }
            if (lane == 0 && rowor)
                atomicOr(&snz[i >> 6], 1ull << (i & 63));
        }
        __syncthreads();

        // sparse chunked greedy scan over actives
        if (tid < 32 && A > 0) {
            const int ln = tid;
            for (int c = 0; c < na; c++) {
                const int base = c << 6;

                if (ln == 0) {
                    u64 kw  = skeepA[c];
                    u64 rem = kw & snz[c];
                    while (rem) {
                        int b = __ffsll((long long)rem) - 1;
                        u64 s = fast ? ssup[(size_t)(base + b) * na + c]
                                     : g_sup[(size_t)(base + b) * na + c];
                        kw  &= ~s;          // bits in s are strictly > b
                        rem &= ~s;
                        rem &= rem - 1;     // clear processed (lowest) bit
                    }
                    skeepA[c] = kw;
                }
                __syncwarp();

                const u64 kwnz = skeepA[c] & snz[c];
                if (kwnz) {
                    for (int w = c + 1 + ln; w < na; w += 32) {
                        u64 acc = 0, t = kwnz;
                        while (t) {
                            int b = __ffsll((long long)t) - 1;
                            t &= t - 1;
                            acc |= fast ? ssup[(size_t)(base + b) * na + w]
                                        : g_sup[(size_t)(base + b) * na + w];
                        }
                        skeepA[w] &= ~acc;
                    }
                }
                __syncwarp();
            }
        }
        __syncthreads();

        // map suppressed actives back to global sorted ranks
        for (int a = tid; a < A; a += NTHR) {
            if (!((skeepA[a >> 6] >> (a & 63)) & 1ull)) {
                int r = samap[a];
                atomicAnd(&skeepR[r >> 6], ~(1ull << (r & 63)));
            }
        }
        __syncthreads();

        // scatter kept rows (output zeroed in P0)
        for (int r = tid; r < M; r += NTHR) {
            if ((skeepR[r >> 6] >> (r & 63)) & 1ull) {
                float4 b = g_sbox[r];
                out[r * 5 + 0] = g_sscore[r];
                out[r * 5 + 1] = b.x;
                out[r * 5 + 2] = b.y;
                out[r * 5 + 3] = b.z - b.x;
                out[r * 5 + 4] = b.w - b.y;
            }
        }
    }

    // ---------------- final: wait for all, reset for next replay -------------
    __syncthreads();
    if (tid == 0) {
        while (*(volatile int*)&g_bar < 2 * NBLK + (NBLK - 1)) { }
        g_cnt  = 0;
        g_acnt = 0;
        g_bar  = 0;
        __threadfence();
    }
}

// ---------------------------------------------------------------------------
extern "C" void kernel_launch(void* const* d_in, const int* in_sizes, int n_in,
                              void* d_out, int out_size)
{
    (void)in_sizes; (void)n_in; (void)out_size;
    const float* x   = (const float*)d_in[0];
    float*       out = (float*)d_out;

    cudaFuncSetAttribute(rbb_fused,
                         cudaFuncAttributeMaxDynamicSharedMemorySize,
                         DSMEM_BYTES);

    rbb_fused<<<NBLK, NTHR, DSMEM_BYTES>>>(x, out);
}

// round 14
// speedup vs baseline: 22.0206x; 1.2262x over previous
#include <cuda_runtime.h>

// ReduceBoundingBoxes: decode + threshold + stable sort + greedy NMS.
// SINGLE persistent kernel, 18 blocks x 1024 threads, TWO software grid
// barriers.
//   P0: zero output, decode + warp-aggregated compaction, act flag + count
//   B1
//   P1: stable rank via packed u64 keys, DUAL-key per warp (shared j loads),
//       packed (r,ra) single warp reduction -> sorted + active arrays.
//   B2  (blocks != 0 then arrive-and-exit)
//   P4: block 0 only: in-SMEM ballot-built suppression bit-matrix over
//       actives (division-free IoU predicate) + sparse chunked greedy scan
//       + map back + scatter.
//   end: block 0 waits for all arrivals, resets counters for next replay.

#define NCELL   9216
#define PDIM    96
#define WIDTHF  3072.0f
#define HEIGHTF 2304.0f
#define XPSF    32.0f    // multiplies ROW index (P dim)
#define YPSF    24.0f    // multiplies COL index (Q dim)
#define MAXNW   144      // ceil(9216/64)
#define NBLK    18
#define NTHR    1024
#define GTOT    (NBLK * NTHR)
#define NWARP   (NBLK * 32)       // 576 grid-wide P1 warps
#define DSMEM_BYTES 184320

typedef unsigned long long u64;

// -------- global scratch (static device memory) ----------------------------
__device__ int    g_cnt;    // valid-box count;  reset at end of every run
__device__ int    g_acnt;   // active-box count; reset at end of every run
__device__ int    g_bar;    // barrier arrivals; reset at end of every run
__device__ float  g_cscore[NCELL];
__device__ float4 g_cbox[NCELL];
__device__ int    g_corig[NCELL];
__device__ unsigned char g_cact[NCELL];
__device__ float  g_sscore[NCELL];
__device__ float4 g_sbox[NCELL];
__device__ float4 g_abox[NCELL];    // active boxes in rank order
__device__ int    g_amap[NCELL];    // active a -> global sorted rank r
__device__ u64    g_sup[(size_t)NCELL * MAXNW];   // fallback only (A large)

extern __shared__ unsigned char dyn_smem[];

__device__ __forceinline__ void grid_barrier(int target)
{
    __syncthreads();
    if (threadIdx.x == 0) {
        __threadfence();
        atomicAdd(&g_bar, 1);
        while (*(volatile int*)&g_bar < target) { }
    }
    __syncthreads();
    __threadfence();
}

__global__ __launch_bounds__(NTHR, 1)
void rbb_fused(const float* __restrict__ x, float* __restrict__ out)
{
    const int tid  = threadIdx.x;
    const int bid  = blockIdx.x;
    const int gtid = bid * NTHR + tid;
    const int wid  = tid >> 5;
    const int lane = tid & 31;

    // ---------------- P0: zero output, decode + compact + act ----------------
    for (int i = gtid; i < (NCELL * 5) / 4; i += GTOT)
        ((float4*)out)[i] = make_float4(0.f, 0.f, 0.f, 0.f);

    for (int c = gtid; c < NCELL; c += GTOT) {
        float s = x[c];
        bool valid = s > 0.9f;
        bool act = false;
        float bx1 = 0.f, by1 = 0.f, bx2 = 0.f, by2 = 0.f;
        if (valid) {
            int   p  = c / PDIM;
            int   q  = c - p * PDIM;
            float ii = (float)p * XPSF;
            float jj = (float)q * YPSF;
            float v1 = x[1 * NCELL + c];
            float v2 = x[2 * NCELL + c];
            float v3 = x[3 * NCELL + c];
            float v4 = x[4 * NCELL + c];
            bx1 = v1 * WIDTHF  + ii;
            by1 = v2 * HEIGHTF + jj;
            bx2 = (v3 - v1) * WIDTHF  + ii;
            by2 = (v4 - v2) * HEIGHTF + jj;
            act = (bx2 > bx1) && (by2 > by1);
        }
        unsigned vmask = __ballot_sync(0xFFFFFFFFu, valid);
        unsigned amask = __ballot_sync(0xFFFFFFFFu, act);
        if (vmask) {
            int leader = __ffs(vmask) - 1;
            int base = 0;
            if (lane == leader) {
                base = atomicAdd(&g_cnt, __popc(vmask));
                if (amask) atomicAdd(&g_acnt, __popc(amask));
            }
            base = __shfl_sync(0xFFFFFFFFu, base, leader);
            if (valid) {
                int k = base + __popc(vmask & ((1u << lane) - 1u));
                g_cscore[k] = s;
                g_cbox[k]   = make_float4(bx1, by1, bx2, by2);
                g_corig[k]  = c;
                g_cact[k]   = act ? 1 : 0;
            }
        }
    }
    grid_barrier(1 * NBLK);

    const int M = *(volatile int*)&g_cnt;
    const int A = *(volatile int*)&g_acnt;

    // ---------------- P1: rank (global + active) via packed u64 keys ---------
    // key = (score_bits << 32) | ~orig: order-isomorphic, unique, nonzero for
    // real entries (score bits ~0x3F6...). Padding key 0 never wins a compare.
    {
        u64*      skey  = (u64*)dyn_smem;                    // [M rounded to 32]
        unsigned* sactw = (unsigned*)(dyn_smem + 73728);     // [ceil(M/32)]

        const int nit = (M + 31) >> 5;       // 32-element j-iterations
        const int M32 = nit << 5;

        for (int i = tid; i < M32; i += NTHR)
            skey[i] = (i < M)
                ? (((u64)__float_as_uint(g_cscore[i]) << 32)
                   | (u64)(0xFFFFFFFFu - (unsigned)g_corig[i]))
                : 0ull;
        // act bitmap (full-warp ballots; uniform trip count)
        for (int t = 0; t < M32; t += NTHR) {
            int i = t + tid;
            bool a = (i < M) && (g_cact[i] != 0);
            unsigned bal = __ballot_sync(0xFFFFFFFFu, a);
            if (lane == 0 && i < M32) sactw[i >> 5] = bal;
        }
        __syncthreads();

        // dual-key per warp: share each skey[j] load between two keys;
        // pack (r, ra) as (r<<16)|ra -> one reduction per key.
        for (int kk = bid * 32 + wid; kk < M; kk += 2 * NWARP) {
            const int kA = kk;
            const int kB = kk + NWARP;
            const bool hasB = (kB < M);
            u64 keyA = skey[kA];
            u64 keyB = hasB ? skey[kB] : ~0ull;   // nothing exceeds ~0ull
            int accA = 0, accB = 0;
            for (int it = 0; it < nit; it++) {
                u64 kj = skey[(it << 5) + lane];
                int w  = 0x10000 | (int)((sactw[it] >> lane) & 1u);
                if (kj > keyA) accA += w;
                if (kj > keyB) accB += w;
            }
            accA = __reduce_add_sync(0xFFFFFFFFu, accA);
            accB = __reduce_add_sync(0xFFFFFFFFu, accB);
            if (lane == 0) {
                {
                    int r = accA >> 16, ra = accA & 0xFFFF;
                    float4 bk = g_cbox[kA];
                    g_sbox[r]   = bk;
                    g_sscore[r] = g_cscore[kA];
                    if (g_cact[kA]) { g_abox[ra] = bk; g_amap[ra] = r; }
                }
                if (hasB) {
                    int r = accB >> 16, ra = accB & 0xFFFF;
                    float4 bk = g_cbox[kB];
                    g_sbox[r]   = bk;
                    g_sscore[r] = g_cscore[kB];
                    if (g_cact[kB]) { g_abox[ra] = bk; g_amap[ra] = r; }
                }
            }
        }
    }
    grid_barrier(2 * NBLK);

    // blocks != 0: arrive and exit (frees SMs; block 0 does the tail alone)
    if (bid != 0) {
        __syncthreads();
        if (tid == 0) { __threadfence(); atomicAdd(&g_bar, 1); }
        return;
    }

    // ---------------- P4 (block 0): in-SMEM matrix + scan + scatter ----------
    {
        __shared__ u64 skeepA[MAXNW];
        __shared__ u64 skeepR[MAXNW];
        __shared__ u64 snz[MAXNW];

        const int na = (A + 63) >> 6;
        // SMEM layout: sabox [0,16A) | samap [16A,20A) | ssup [align8(20A),..)
        float4* sabox = (float4*)dyn_smem;
        int*    samap = (int*)(dyn_smem + (size_t)A * 16);
        size_t  supoff = ((size_t)A * 20 + 7) & ~(size_t)7;
        u64*    ssup  = (u64*)(dyn_smem + supoff);
        const bool fast = (supoff + (size_t)A * na * 8) <= DSMEM_BYTES;

        for (int a = tid; a < A; a += NTHR) {
            sabox[a] = g_abox[a];
            samap[a] = g_amap[a];
        }
        if (tid < MAXNW) {
            snz[tid] = 0ull;
            if (tid < na) {
                int nb = A - (tid << 6);
                skeepA[tid] = (nb >= 64) ? ~0ull : ((1ull << nb) - 1ull);
            }
            int nwR = (M + 63) >> 6;
            if (tid < nwR) {
                int nb = M - (tid << 6);
                skeepR[tid] = (nb >= 64) ? ~0ull : ((1ull << nb) - 1ull);
            }
        }
        __syncthreads();

        // build suppression bit-matrix via warp ballots (warp-per-row).
        // Division-free predicate: denom = ai+aj-inter+1e-9 > 0, so
        // inter/denom > 0.5  <=>  inter > 0.5*denom.
        for (int i = wid; i < A; i += 32) {
            float4 bi = sabox[i];
            float  ai = (bi.z - bi.x) * (bi.w - bi.y);
            u64 rowor = 0;
            for (int w = (i >> 6); w < na; w++) {
                int j1 = (w << 6) + lane;
                int j2 = j1 + 32;
                bool p1 = false, p2 = false;
                if (j1 > i && j1 < A) {
                    float4 bj = sabox[j1];
                    float  aj = (bj.z - bj.x) * (bj.w - bj.y);
                    float iw = fmaxf(fminf(bi.z, bj.z) - fmaxf(bi.x, bj.x), 0.0f);
                    float ih = fmaxf(fminf(bi.w, bj.w) - fmaxf(bi.y, bj.y), 0.0f);
                    float inter = iw * ih;
                    p1 = inter > 0.5f * (ai + aj - inter + 1e-9f);
                }
                if (j2 > i && j2 < A) {
                    float4 bj = sabox[j2];
                    float  aj = (bj.z - bj.x) * (bj.w - bj.y);
                    float iw = fmaxf(fminf(bi.z, bj.z) - fmaxf(bi.x, bj.x), 0.0f);
                    float ih = fmaxf(fminf(bi.w, bj.w) - fmaxf(bi.y, bj.y), 0.0f);
                    float inter = iw * ih;
                    p2 = inter > 0.5f * (ai + aj - inter + 1e-9f);
                }
                unsigned lo = __ballot_sync(0xFFFFFFFFu, p1);
                unsigned hi = __ballot_sync(0xFFFFFFFFu, p2);
                u64 bits = (u64)lo | ((u64)hi << 32);
                if (lane == 0) {
                    if (fast) ssup[(size_t)i * na + w] = bits;
                    else      g_sup[(size_t)i * na + w] = bits;
                }
                rowor |= bits;
            }
            if (lane == 0 && rowor)
                atomicOr(&snz[i >> 6], 1ull << (i & 63));
        }
        __syncthreads();

        // sparse chunked greedy scan over actives
        if (tid < 32 && A > 0) {
            const int ln = tid;
            for (int c = 0; c < na; c++) {
                const int base = c << 6;

                if (ln == 0) {
                    u64 kw  = skeepA[c];
                    u64 rem = kw & snz[c];
                    while (rem) {
                        int b = __ffsll((long long)rem) - 1;
                        u64 s = fast ? ssup[(size_t)(base + b) * na + c]
                                     : g_sup[(size_t)(base + b) * na + c];
                        kw  &= ~s;          // bits in s are strictly > b
                        rem &= ~s;
                        rem &= rem - 1;     // clear processed (lowest) bit
                    }
                    skeepA[c] = kw;
                }
                __syncwarp();

                const u64 kwnz = skeepA[c] & snz[c];
                if (kwnz) {
                    for (int w = c + 1 + ln; w < na; w += 32) {
                        u64 acc = 0, t = kwnz;
                        while (t) {
                            int b = __ffsll((long long)t) - 1;
                            t &= t - 1;
                            acc |= fast ? ssup[(size_t)(base + b) * na + w]
                                        : g_sup[(size_t)(base + b) * na + w];
                        }
                        skeepA[w] &= ~acc;
                    }
                }
                __syncwarp();
            }
        }
        __syncthreads();

        // map suppressed actives back to global sorted ranks
        for (int a = tid; a < A; a += NTHR) {
            if (!((skeepA[a >> 6] >> (a & 63)) & 1ull)) {
                int r = samap[a];
                atomicAnd(&skeepR[r >> 6], ~(1ull << (r & 63)));
            }
        }
        __syncthreads();

        // scatter kept rows (output zeroed in P0)
        for (int r = tid; r < M; r += NTHR) {
            if ((skeepR[r >> 6] >> (r & 63)) & 1ull) {
                float4 b = g_sbox[r];
                out[r * 5 + 0] = g_sscore[r];
                out[r * 5 + 1] = b.x;
                out[r * 5 + 2] = b.y;
                out[r * 5 + 3] = b.z - b.x;
                out[r * 5 + 4] = b.w - b.y;
            }
        }
    }

    // ---------------- final: wait for all, reset for next replay -------------
    __syncthreads();
    if (tid == 0) {
        while (*(volatile int*)&g_bar < 2 * NBLK + (NBLK - 1)) { }
        g_cnt  = 0;
        g_acnt = 0;
        g_bar  = 0;
        __threadfence();
    }
}

// ---------------------------------------------------------------------------
extern "C" void kernel_launch(void* const* d_in, const int* in_sizes, int n_in,
                              void* d_out, int out_size)
{
    (void)in_sizes; (void)n_in; (void)out_size;
    const float* x   = (const float*)d_in[0];
    float*       out = (float*)d_out;

    cudaFuncSetAttribute(rbb_fused,
                         cudaFuncAttributeMaxDynamicSharedMemorySize,
                         DSMEM_BYTES);

    rbb_fused<<<NBLK, NTHR, DSMEM_BYTES>>>(x, out);
}